// round 13
// baseline (speedup 1.0000x reference)
#include <cuda_runtime.h>
#include <cuda_bf16.h>
#include <cuda_fp16.h>
#include <math.h>

typedef unsigned long long ull;
typedef unsigned int uint;

#define MAXN 131072
#define MAXE 262144
#define MAXB 4096

// ---------------- device scratch ----------------
__device__ float g_msum[(size_t)MAXN * 64];
__device__ float g_cnt[MAXN];              // reused as attention e-buffer later
__device__ float g_out[(size_t)MAXN * 64];
__device__ float g_S[MAXB * 192];          // per graph: [0:128]=q_star, [128:192]=hl
__device__ float g_cl[MAXB * 64];
__device__ int   g_seg[MAXB + 1];
// edge GEMM: fp16 w_e2 (single), per-chunk smem images (16 chunks x 16384 B)
__device__ unsigned char g_W2hi[16 * 16384];
// GRU GEMM: Wg fp16 smem image [256 rows x 128 B], epilogue-friendly col order
__device__ unsigned char g_GBhi[32768];
__device__ float g_gbias[256];

// ---------------- helpers ----------------
__device__ __forceinline__ float fast_sigm(float x) {
    x = fminf(fmaxf(x, -30.0f), 30.0f);
    return __fdividef(1.0f, 1.0f + __expf(-x));
}
__device__ __forceinline__ float fast_tanh(float x) {
    x = fminf(fmaxf(x, -15.0f), 15.0f);
    float t = __expf(2.0f * x);
    return 1.0f - __fdividef(2.0f, 1.0f + t);
}
__device__ __forceinline__ uint smem_u32(const void* p) {
    uint a; asm("{ .reg .u64 t; cvta.to.shared.u64 t, %1; cvt.u32.u64 %0, t; }" : "=r"(a) : "l"(p));
    return a;
}
__device__ __forceinline__ void ldsm4(uint* r, uint addr) {
    asm volatile("ldmatrix.sync.aligned.m8n8.x4.shared.b16 {%0,%1,%2,%3}, [%4];"
        : "=r"(r[0]), "=r"(r[1]), "=r"(r[2]), "=r"(r[3]) : "r"(addr));
}
__device__ __forceinline__ void mma16816(float* d, const uint* a, const uint* b) {
    asm volatile("mma.sync.aligned.m16n8k16.row.col.f32.f16.f16.f32 "
        "{%0,%1,%2,%3}, {%4,%5,%6,%7}, {%8,%9}, {%0,%1,%2,%3};"
        : "+f"(d[0]), "+f"(d[1]), "+f"(d[2]), "+f"(d[3])
        : "r"(a[0]), "r"(a[1]), "r"(a[2]), "r"(a[3]), "r"(b[0]), "r"(b[1]));
}
__device__ __forceinline__ void cp16(uint dst, const void* src) {
    asm volatile("cp.async.ca.shared.global [%0], [%1], 16;" :: "r"(dst), "l"(src));
}
__device__ __forceinline__ void red2(float* p, float a, float b) {
    asm volatile("red.global.add.v2.f32 [%0], {%1, %2};" :: "l"(p), "f"(a), "f"(b) : "memory");
}

// ---------------- zero scratch ----------------
__global__ void zero_kernel(int N, int B) {
    int idx = blockIdx.x * blockDim.x + threadIdx.x;
    int stride = gridDim.x * blockDim.x;
    float4 z4 = make_float4(0.f, 0.f, 0.f, 0.f);
    int nm4 = N * 16;
    float4* m4 = (float4*)g_msum;
    for (int i = idx; i < nm4; i += stride) m4[i] = z4;
    for (int i = idx; i < N; i += stride) g_cnt[i] = 0.0f;
    int ns = B * 192;
    for (int i = idx; i < ns; i += stride) g_S[i] = 0.0f;
    int nc = B * 64;
    for (int i = idx; i < nc; i += stride) g_cl[i] = 0.0f;
}

// ---------------- segment offsets ----------------
__global__ void seg_kernel(const int* __restrict__ batch, int N, int B) {
    int b = blockIdx.x * blockDim.x + threadIdx.x;
    if (b > B) return;
    int lo = 0, hi = N;
    while (lo < hi) { int mid = (lo + hi) >> 1; if (batch[mid] < b) lo = mid + 1; else hi = mid; }
    g_seg[b] = lo;
}

// ---------------- merged prep ----------------
// GRU col mapping (epilogue-friendly): col c -> (j, gate):
//   w=c>>6, rem=c&63, half=rem>>5, within=rem&31, tile=within>>3, colin=within&7
//   j = w*16 + tile*4 + (colin>>1); gate = half*2 + (colin&1)  [0=r,1=z,2=inn,3=hn]
__device__ __forceinline__ void gru_col_decode(int c, int& j, int& gate) {
    int w = c >> 6, rem = c & 63;
    int half = rem >> 5, within = rem & 31;
    int tile = within >> 3, colin = within & 7;
    j = w * 16 + tile * 4 + (colin >> 1);
    gate = half * 2 + (colin & 1);
}

__global__ void prep_kernel(const float* __restrict__ w_e2,
                            const float* __restrict__ wih, const float* __restrict__ whh,
                            const float* __restrict__ bih, const float* __restrict__ bhh) {
    int bid = blockIdx.x;
    if (bid < 512) {
        int idx = bid * 256 + threadIdx.x;
        int m = idx >> 10, j = idx & 1023;     // m = k, j = d*64+h
        __half hi = __float2half_rn(w_e2[idx]);
        int nc = j >> 6, r = j & 63;
        int c = m >> 3;
        int off = r * 256 + ((c ^ (r & 7)) << 4) + (m & 7) * 2;
        *(__half*)(g_W2hi + nc * 16384 + off) = hi;
    } else {
        int idx = (bid - 512) * 256 + threadIdx.x;
        if (idx < 16384) {
            int c = idx >> 6, k = idx & 63;
            int j, gate;
            gru_col_decode(c, j, gate);
            float v;
            if (gate == 0)      v = wih[j * 64 + k] + whh[j * 64 + k];
            else if (gate == 1) v = wih[(64 + j) * 64 + k] + whh[(64 + j) * 64 + k];
            else if (gate == 2) v = wih[(128 + j) * 64 + k];
            else                v = whh[(128 + j) * 64 + k];
            __half hi = __float2half_rn(v);
            int off = c * 128 + (((k >> 3) ^ (c & 7)) << 4) + (k & 7) * 2;
            *(__half*)(g_GBhi + off) = hi;
        } else if (idx < 16640) {
            int c = idx - 16384;
            int j, gate;
            gru_col_decode(c, j, gate);
            float v;
            if (gate == 0)      v = bih[j] + bhh[j];
            else if (gate == 1) v = bih[64 + j] + bhh[64 + j];
            else if (gate == 2) v = bih[128 + j];
            else                v = bhh[128 + j];
            g_gbias[c] = v;
        }
    }
}

// ---------------- edge kernel: HMMA, A register-resident across chunks ----------------
#define O_A   0          // 32768 (A hid fp16, 128 rows x 256 B)
#define O_B   32768      // 2 x 16384 double buffer
#define O_XT  65536      // 8192  (xT [16][128] f32)
#define O_B2  73728      // 4096  (b_e2 1024 f32)
#define O_DST 77824      // 512
#define EK3_SMEM 78336

__global__ void __launch_bounds__(256, 1) edge_kernel3(
    const float* __restrict__ x, const float* __restrict__ edge_attr,
    const int* __restrict__ edge_index,
    const float* __restrict__ w_e1, const float* __restrict__ b_e1,
    const float* __restrict__ b_e2, int E)
{
    extern __shared__ char sm[];
    uint smb = smem_u32(sm);
    float* xT  = (float*)(sm + O_XT);
    float* b2S = (float*)(sm + O_B2);
    int*  dstS = (int*)(sm + O_DST);

    int t = threadIdx.x;
    int wid = t >> 5, lane = t & 31;
    int mw = wid & 3, nw = wid >> 2;
    int e0 = blockIdx.x * 128;

    // prefetch B chunk 0 (16 KB)
    {
        uint dst = smb + O_B + t * 16;
        const char* sh = (const char*)g_W2hi + t * 16;
        #pragma unroll
        for (int i = 0; i < 4; ++i) cp16(dst + i * 4096, sh + i * 4096);
        asm volatile("cp.async.commit_group;");
    }

    for (int i = t; i < 1024; i += 256) b2S[i] = b_e2[i];

    if (t < 128) {
        int e = e0 + t;
        int dd = -1;
        if (e < E) {
            int s = edge_index[e];
            dd = edge_index[E + e];
            const float4* xr = reinterpret_cast<const float4*>(x + (size_t)s * 16);
            #pragma unroll
            for (int q = 0; q < 4; ++q) {
                float4 v = xr[q];
                xT[(q * 4 + 0) * 128 + t] = v.x;
                xT[(q * 4 + 1) * 128 + t] = v.y;
                xT[(q * 4 + 2) * 128 + t] = v.z;
                xT[(q * 4 + 3) * 128 + t] = v.w;
            }
            atomicAdd(&g_cnt[dd], 1.0f);
        } else {
            #pragma unroll
            for (int q = 0; q < 16; ++q) xT[q * 128 + t] = 0.0f;
        }
        dstS[t] = dd;
    }

    // form A = fp16(hid)
    {
        int row = t >> 1;
        int cbase = (t & 1) * 8;
        int e = e0 + row;
        float ea0 = 0.f, ea1 = 0.f, ea2 = 0.f, ea3 = 0.f;
        if (e < E) {
            float4 ea = reinterpret_cast<const float4*>(edge_attr)[e];
            ea0 = ea.x; ea1 = ea.y; ea2 = ea.z; ea3 = ea.w;
        }
        #pragma unroll
        for (int c = cbase; c < cbase + 8; ++c) {
            uint h4[4];
            #pragma unroll
            for (int p = 0; p < 4; ++p) {
                int k0 = c * 8 + p * 2;
                float2 w0 = __ldg((const float2*)(w_e1 + k0));
                float2 w1 = __ldg((const float2*)(w_e1 + 128 + k0));
                float2 w2 = __ldg((const float2*)(w_e1 + 256 + k0));
                float2 w3 = __ldg((const float2*)(w_e1 + 384 + k0));
                float2 bb = __ldg((const float2*)(b_e1 + k0));
                float h0 = fmaf(ea3, w3.x, fmaf(ea2, w2.x, fmaf(ea1, w1.x, fmaf(ea0, w0.x, bb.x))));
                float h1 = fmaf(ea3, w3.y, fmaf(ea2, w2.y, fmaf(ea1, w1.y, fmaf(ea0, w0.y, bb.y))));
                __half2 hh = __floats2half2_rn(fmaxf(h0, 0.0f), fmaxf(h1, 0.0f));
                h4[p] = *reinterpret_cast<uint*>(&hh);
            }
            int off = row * 256 + ((c ^ (row & 7)) << 4);
            *(uint4*)(sm + O_A + off) = make_uint4(h4[0], h4[1], h4[2], h4[3]);
        }
    }
    __syncthreads();

    // hoist A fragments into registers ONCE (invariant across all 16 chunks)
    uint afr[8][8];
    {
        uint smA = smb + O_A;
        int mi = lane >> 3;
        int arow = mw * 32 + (lane & 7) + (mi & 1) * 8;
        #pragma unroll
        for (int kt = 0; kt < 8; ++kt) {
            int ac = 2 * kt + (mi >> 1);
            uint addr = smA + arow * 256 + ((ac ^ (arow & 7)) << 4);
            ldsm4(&afr[kt][0], addr);
            ldsm4(&afr[kt][4], addr + 16 * 256);
        }
    }

    float macc[2][4][4];
    #pragma unroll
    for (int a = 0; a < 2; ++a)
        #pragma unroll
        for (int b = 0; b < 4; ++b)
            #pragma unroll
            for (int r = 0; r < 4; ++r) macc[a][b][r] = 0.0f;

    for (int nc = 0; nc < 16; ++nc) {
        asm volatile("cp.async.wait_group 0;" ::: "memory");
        __syncthreads();
        uint smBbuf = smb + O_B + (nc & 1) * 16384;

        if (nc < 15) {
            uint dst = smb + O_B + ((nc + 1) & 1) * 16384 + t * 16;
            const char* sh = (const char*)g_W2hi + (nc + 1) * 16384 + t * 16;
            #pragma unroll
            for (int i = 0; i < 4; ++i) cp16(dst + i * 4096, sh + i * 4096);
            asm volatile("cp.async.commit_group;");
        }

        float dacc[2][4][4];
        #pragma unroll
        for (int a = 0; a < 2; ++a)
            #pragma unroll
            for (int b = 0; b < 4; ++b)
                #pragma unroll
                for (int r = 0; r < 4; ++r) dacc[a][b][r] = 0.0f;

        #pragma unroll
        for (int kt = 0; kt < 8; ++kt) {
            uint bh[2][4];
            {
                int mi = lane >> 3;
                int nrow = nw * 32 + (mi >> 1) * 8 + (lane & 7);
                int bc = 2 * kt + (mi & 1);
                uint aH = smBbuf + nrow * 256 + ((bc ^ (nrow & 7)) << 4);
                ldsm4(bh[0], aH);
                ldsm4(bh[1], aH + 4096);
            }
            #pragma unroll
            for (int mt = 0; mt < 2; ++mt) {
                const uint* av = &afr[kt][mt * 4];
                #pragma unroll
                for (int ng = 0; ng < 2; ++ng) {
                    #pragma unroll
                    for (int s = 0; s < 2; ++s)
                        mma16816(dacc[mt][ng * 2 + s], av, &bh[ng][s * 2]);
                }
            }
        }

        // epilogue: msg += x[e,nc] * (D + b_e2)
        {
            int rb = mw * 32 + (lane >> 2);
            float xv00 = xT[nc * 128 + rb];
            float xv01 = xT[nc * 128 + rb + 8];
            float xv10 = xT[nc * 128 + rb + 16];
            float xv11 = xT[nc * 128 + rb + 24];
            #pragma unroll
            for (int mt = 0; mt < 2; ++mt) {
                float xa = mt ? xv10 : xv00;
                float xb = mt ? xv11 : xv01;
                #pragma unroll
                for (int nt = 0; nt < 4; ++nt) {
                    int col = nw * 32 + nt * 8 + 2 * (lane & 3);
                    float b0v = b2S[nc * 64 + col];
                    float b1v = b2S[nc * 64 + col + 1];
                    macc[mt][nt][0] = fmaf(xa, dacc[mt][nt][0] + b0v, macc[mt][nt][0]);
                    macc[mt][nt][1] = fmaf(xa, dacc[mt][nt][1] + b1v, macc[mt][nt][1]);
                    macc[mt][nt][2] = fmaf(xb, dacc[mt][nt][2] + b0v, macc[mt][nt][2]);
                    macc[mt][nt][3] = fmaf(xb, dacc[mt][nt][3] + b1v, macc[mt][nt][3]);
                }
            }
        }
    }

    // scatter: vectorized reductions (red.v2)
    #pragma unroll
    for (int mt = 0; mt < 2; ++mt) {
        #pragma unroll
        for (int half = 0; half < 2; ++half) {
            int row = mw * 32 + mt * 16 + (lane >> 2) + half * 8;
            int dd = dstS[row];
            if (dd < 0) continue;
            float* mr = g_msum + (size_t)dd * 64;
            #pragma unroll
            for (int nt = 0; nt < 4; ++nt) {
                int col = nw * 32 + nt * 8 + 2 * (lane & 3);
                red2(mr + col, macc[mt][nt][half * 2], macc[mt][nt][half * 2 + 1]);
            }
        }
    }
}

// ---------------- fused node + GRU x3 via HMMA (single-pass fp16, 2m x 4n grid) ----------------
#define G_HS   0        // 64 x 65 f32 = 16640 (col 64 = cnt)
#define G_AHI  16640    // 8192 (overlay: root 4096 + xS 4096 during node phase)
#define G_BHI  24832    // 32768
#define G_BIAS 57600    // 1024
#define GRU_SMEM 58624

__global__ void __launch_bounds__(256, 2) gru_node_kernel(
    const float* __restrict__ x, const float* __restrict__ root,
    const float* __restrict__ conv_bias, int N)
{
    extern __shared__ char sm2[];
    uint smb = smem_u32(sm2);
    float* hS    = (float*)(sm2 + G_HS);
    float* biasS = (float*)(sm2 + G_BIAS);
    float* rootS = (float*)(sm2 + G_AHI);          // node-phase overlay
    float* xS    = (float*)(sm2 + G_AHI + 4096);

    int t = threadIdx.x, wid = t >> 5, lane = t & 31;
    int n0 = blockIdx.x * 64;

    // stage B (32 KB) asynchronously — overlaps node phase
    {
        uint dh = smb + G_BHI + t * 16;
        const char* sh = (const char*)g_GBhi + t * 16;
        #pragma unroll
        for (int i = 0; i < 8; ++i) cp16(dh + i * 4096, sh + i * 4096);
        asm volatile("cp.async.commit_group;");
    }
    biasS[t] = g_gbias[t];

    // node-phase staging
    for (int i = t; i < 1024; i += 256) rootS[i] = root[i];
    for (int i = t; i < 1024; i += 256) {
        int r = i >> 4, d = i & 15;
        int n = n0 + r;
        xS[i] = (n < N) ? x[(size_t)n * 16 + d] : 0.0f;
    }
    if (t < 64) {
        int n = n0 + t;
        hS[t * 65 + 64] = (n < N) ? fmaxf(g_cnt[n], 1.0f) : 1.0f;
    }
    __syncthreads();

    // node update: hS = relu(msum/cnt + x@root + conv_bias)
    {
        float cbv = __ldg(conv_bias + (t & 63));
        #pragma unroll
        for (int j = 0; j < 16; ++j) {
            int idx = j * 256 + t;
            int r = idx >> 6, c = idx & 63;
            int n = n0 + r;
            float v = 0.0f;
            if (n < N) {
                float acc = cbv;
                const float* xr = xS + r * 16;
                #pragma unroll
                for (int d = 0; d < 16; ++d) acc = fmaf(xr[d], rootS[d * 64 + c], acc);
                v = fmaxf(g_msum[(size_t)n * 64 + c] / hS[r * 65 + 64] + acc, 0.0f);
            }
            hS[r * 65 + c] = v;
        }
    }
    asm volatile("cp.async.wait_group 0;" ::: "memory");
    __syncthreads();

    int mw = wid & 1, nh = wid >> 1;
    int mi = lane >> 3;
    uint smAhi = smb + G_AHI;
    uint smBh = smb + G_BHI;

    for (int step = 0; step < 3; ++step) {
        // convert hS -> fp16 A
        {
            int r = t >> 2, q = t & 3;
            const float* hr = hS + r * 65 + q * 16;
            #pragma unroll
            for (int c2 = 0; c2 < 2; ++c2) {
                uint hi4[4];
                #pragma unroll
                for (int p = 0; p < 4; ++p) {
                    __half2 hh = __floats2half2_rn(hr[c2 * 8 + p * 2], hr[c2 * 8 + p * 2 + 1]);
                    hi4[p] = *reinterpret_cast<uint*>(&hh);
                }
                int cc = q * 2 + c2;
                int off = r * 128 + ((cc ^ (r & 7)) << 4);
                *(uint4*)(sm2 + G_AHI + off) = make_uint4(hi4[0], hi4[1], hi4[2], hi4[3]);
            }
        }
        __syncthreads();

        float acc[16][4];
        #pragma unroll
        for (int i = 0; i < 16; ++i)
            #pragma unroll
            for (int j = 0; j < 4; ++j) acc[i][j] = 0.0f;

        #pragma unroll
        for (int kt = 0; kt < 4; ++kt) {
            uint a0[4], a1[4];
            {
                int arow = mw * 32 + (lane & 7) + (mi & 1) * 8;
                int ac = 2 * kt + (mi >> 1);
                uint aoff = (uint)(arow * 128 + ((ac ^ (arow & 7)) << 4));
                ldsm4(a0, smAhi + aoff);
                ldsm4(a1, smAhi + aoff + 16 * 128);
            }
            #pragma unroll
            for (int g2 = 0; g2 < 4; ++g2) {
                uint bh[4];
                int nrow = nh * 64 + g2 * 16 + (mi >> 1) * 8 + (lane & 7);
                int bc = 2 * kt + (mi & 1);
                uint boff = (uint)(nrow * 128 + ((bc ^ (nrow & 7)) << 4));
                ldsm4(bh, smBh + boff);
                mma16816(acc[0 * 8 + g2 * 2],     a0, bh);
                mma16816(acc[0 * 8 + g2 * 2 + 1], a0, bh + 2);
                mma16816(acc[1 * 8 + g2 * 2],     a1, bh);
                mma16816(acc[1 * 8 + g2 * 2 + 1], a1, bh + 2);
            }
        }
        __syncthreads();   // A reads complete before h' overwrite

        // gates -> h' (no shuffles: rz tiles 0..3 pair with inhn tiles 4..7, same lane/j)
        {
            int qj = lane & 3;
            int rb = lane >> 2;
            #pragma unroll
            for (int mt = 0; mt < 2; ++mt) {
                #pragma unroll
                for (int tp = 0; tp < 4; ++tp) {
                    float* aRZ = acc[mt * 8 + tp];
                    float* aNH = acc[mt * 8 + tp + 4];
                    int cb = nh * 64 + tp * 8 + 2 * qj;
                    float br = biasS[cb],      bz = biasS[cb + 1];
                    float bi = biasS[cb + 32], bn = biasS[cb + 33];
                    int j = nh * 16 + tp * 4 + qj;
                    int ra = mw * 32 + mt * 16 + rb;
                    {
                        float r = fast_sigm(aRZ[0] + br), z = fast_sigm(aRZ[1] + bz);
                        float nv = fast_tanh((aNH[0] + bi) + r * (aNH[1] + bn));
                        float hold = hS[ra * 65 + j];
                        hS[ra * 65 + j] = (1.0f - z) * nv + z * hold;
                    }
                    {
                        float r = fast_sigm(aRZ[2] + br), z = fast_sigm(aRZ[3] + bz);
                        float nv = fast_tanh((aNH[2] + bi) + r * (aNH[3] + bn));
                        float hold = hS[(ra + 8) * 65 + j];
                        hS[(ra + 8) * 65 + j] = (1.0f - z) * nv + z * hold;
                    }
                }
            }
        }
        __syncthreads();
    }

    // coalesced writeback
    #pragma unroll
    for (int j = 0; j < 16; ++j) {
        int idx = j * 256 + t;
        int r = idx >> 6, c = idx & 63;
        int n = n0 + r;
        if (n < N) g_out[(size_t)n * 64 + c] = hS[r * 65 + c];
    }
}

// ---------------- Set2Set LSTM step ----------------
__global__ void __launch_bounds__(256) lstm_kernel(
    const float* __restrict__ wih, const float* __restrict__ whh,
    const float* __restrict__ bih, const float* __restrict__ bhh, int B)
{
    __shared__ float wst[256 * 33];
    __shared__ float qsm[8 * 128];
    __shared__ float hsm[8 * 64];
    __shared__ float gsm[8 * 256];
    int t = threadIdx.x;
    int b0 = blockIdx.x * 8;

    for (int i = t; i < 8 * 128; i += 256) {
        int g = i >> 7, k = i & 127;
        qsm[i] = (b0 + g < B) ? g_S[(b0 + g) * 192 + k] : 0.0f;
    }
    for (int i = t; i < 8 * 64; i += 256) {
        int g = i >> 6, k = i & 63;
        hsm[i] = (b0 + g < B) ? g_S[(b0 + g) * 192 + 128 + k] : 0.0f;
    }

    float acc[8];
    float bsum = bih[t] + bhh[t];
    #pragma unroll
    for (int g = 0; g < 8; ++g) acc[g] = bsum;

    for (int c = 0; c < 4; ++c) {
        __syncthreads();
        for (int i = t; i < 8192; i += 256) {
            int j = i >> 5, kk = i & 31;
            wst[j * 33 + kk] = wih[j * 128 + c * 32 + kk];
        }
        __syncthreads();
        #pragma unroll 8
        for (int kk = 0; kk < 32; ++kk) {
            float w = wst[t * 33 + kk];
            #pragma unroll
            for (int g = 0; g < 8; ++g)
                acc[g] = fmaf(w, qsm[g * 128 + c * 32 + kk], acc[g]);
        }
    }
    for (int c = 0; c < 2; ++c) {
        __syncthreads();
        for (int i = t; i < 8192; i += 256) {
            int j = i >> 5, kk = i & 31;
            wst[j * 33 + kk] = whh[j * 64 + c * 32 + kk];
        }
        __syncthreads();
        #pragma unroll 8
        for (int kk = 0; kk < 32; ++kk) {
            float w = wst[t * 33 + kk];
            #pragma unroll
            for (int g = 0; g < 8; ++g)
                acc[g] = fmaf(w, hsm[g * 64 + c * 32 + kk], acc[g]);
        }
    }

    #pragma unroll
    for (int g = 0; g < 8; ++g) gsm[g * 256 + t] = acc[g];
    __syncthreads();

    for (int i = t; i < 8 * 64; i += 256) {
        int g = i >> 6, hh = i & 63;
        int b = b0 + g;
        if (b >= B) continue;
        float ig = fast_sigm(gsm[g * 256 + hh]);
        float fg = fast_sigm(gsm[g * 256 + 64 + hh]);
        float gg = fast_tanh(gsm[g * 256 + 128 + hh]);
        float og = fast_sigm(gsm[g * 256 + 192 + hh]);
        float cnew = fg * g_cl[b * 64 + hh] + ig * gg;
        g_cl[b * 64 + hh] = cnew;
        g_S[b * 192 + 128 + hh] = og * fast_tanh(cnew);
    }
}

// ---------------- Set2Set attention step (128 threads / graph) ----------------
__global__ void __launch_bounds__(128) attn_kernel(int B)
{
    __shared__ float qs[64];
    __shared__ float wm[4], ws[4];
    __shared__ float rgS[64];
    int t = threadIdx.x, b = blockIdx.x;
    if (t < 64) qs[t] = g_S[b * 192 + 128 + t];
    __syncthreads();
    int n0 = g_seg[b], n1 = g_seg[b + 1];
    int w = t >> 5, lid = t & 31;

    float mr = -1e30f, sr = 0.0f;
    for (int n = n0 + w; n < n1; n += 4) {
        const float* orow = g_out + (size_t)n * 64;
        float p = orow[lid] * qs[lid] + orow[32 + lid] * qs[32 + lid];
        #pragma unroll
        for (int off = 16; off; off >>= 1) p += __shfl_xor_sync(0xffffffffu, p, off);
        if (lid == 0) g_cnt[n] = p;
        if (p > mr) { sr *= __expf(mr - p); mr = p; }
        sr += __expf(p - mr);
    }
    if (lid == 0) { wm[w] = mr; ws[w] = sr; }
    __syncthreads();
    float m = fmaxf(fmaxf(wm[0], wm[1]), fmaxf(wm[2], wm[3]));
    float denom = ws[0] * __expf(wm[0] - m) + ws[1] * __expf(wm[1] - m)
                + ws[2] * __expf(wm[2] - m) + ws[3] * __expf(wm[3] - m);

    int col = t & 63, half = t >> 6;
    float rg = 0.0f;
    for (int n = n0 + half; n < n1; n += 2)
        rg = fmaf(__expf(g_cnt[n] - m), g_out[(size_t)n * 64 + col], rg);
    if (half) rgS[col] = rg;
    __syncthreads();
    if (!half) {
        rg += rgS[col];
        if (n1 > n0) rg /= denom;
        g_S[b * 192 + col]      = qs[col];
        g_S[b * 192 + 64 + col] = rg;
    }
}

// ---------------- readout ----------------
__global__ void __launch_bounds__(64) readout_kernel(
    const float* __restrict__ fc1_w, const float* __restrict__ fc1_b,
    const float* __restrict__ fc2_w, const float* __restrict__ fc2_b,
    float* __restrict__ y, int B)
{
    __shared__ float qsm[8 * 128];
    __shared__ float red[2];
    int t = threadIdx.x;
    int b0 = blockIdx.x * 8;
    for (int i = t; i < 1024; i += 64) {
        int g = i >> 7, k = i & 127;
        qsm[i] = (b0 + g < B) ? g_S[(b0 + g) * 192 + k] : 0.0f;
    }
    __syncthreads();
    float w2 = fc2_w[t];
    float b1 = fc1_b[t];
    for (int g = 0; g < 8; ++g) {
        float a = b1;
        #pragma unroll 8
        for (int k = 0; k < 128; ++k) a = fmaf(qsm[g * 128 + k], fc1_w[k * 64 + t], a);
        a = fmaxf(a, 0.0f);
        float p = a * w2;
        #pragma unroll
        for (int off = 16; off; off >>= 1) p += __shfl_xor_sync(0xffffffffu, p, off);
        if ((t & 31) == 0) red[t >> 5] = p;
        __syncthreads();
        if (t == 0 && b0 + g < B) y[b0 + g] = red[0] + red[1] + fc2_b[0];
        __syncthreads();
    }
}

// ---------------- launch ----------------
extern "C" void kernel_launch(void* const* d_in, const int* in_sizes, int n_in,
                              void* d_out, int out_size)
{
    const float* x         = (const float*)d_in[0];
    const float* edge_attr = (const float*)d_in[1];
    const int*   edge_index= (const int*)  d_in[2];
    const int*   batch     = (const int*)  d_in[3];
    const float* w_e1      = (const float*)d_in[4];
    const float* b_e1      = (const float*)d_in[5];
    const float* w_e2      = (const float*)d_in[6];
    const float* b_e2      = (const float*)d_in[7];
    const float* root      = (const float*)d_in[8];
    const float* conv_bias = (const float*)d_in[9];
    const float* gru_wih   = (const float*)d_in[10];
    const float* gru_whh   = (const float*)d_in[11];
    const float* gru_bih   = (const float*)d_in[12];
    const float* gru_bhh   = (const float*)d_in[13];
    const float* lstm_wih  = (const float*)d_in[14];
    const float* lstm_whh  = (const float*)d_in[15];
    const float* lstm_bih  = (const float*)d_in[16];
    const float* lstm_bhh  = (const float*)d_in[17];
    const float* fc1_w     = (const float*)d_in[18];
    const float* fc1_b     = (const float*)d_in[19];
    const float* fc2_w     = (const float*)d_in[20];
    const float* fc2_b     = (const float*)d_in[21];
    float* y = (float*)d_out;

    int N = in_sizes[0] / 16;
    int E = in_sizes[1] / 4;
    int B = out_size;

    static int smem_set = 0;
    if (!smem_set) {
        cudaFuncSetAttribute(edge_kernel3, cudaFuncAttributeMaxDynamicSharedMemorySize, EK3_SMEM);
        cudaFuncSetAttribute(gru_node_kernel, cudaFuncAttributeMaxDynamicSharedMemorySize, GRU_SMEM);
        smem_set = 1;
    }

    // edge_kernel3 is the 4th launch (ncu capture window) this round.
    prep_kernel<<<577, 256>>>(w_e2, gru_wih, gru_whh, gru_bih, gru_bhh);
    zero_kernel<<<1024, 256>>>(N, B);
    seg_kernel<<<(B + 1 + 127) / 128, 128>>>(batch, N, B);
    edge_kernel3<<<(E + 127) / 128, 256, EK3_SMEM>>>(x, edge_attr, edge_index, w_e1, b_e1, b_e2, E);
    gru_node_kernel<<<(N + 63) / 64, 256, GRU_SMEM>>>(x, root, conv_bias, N);
    for (int i = 0; i < 3; ++i) {
        lstm_kernel<<<(B + 7) / 8, 256>>>(lstm_wih, lstm_whh, lstm_bih, lstm_bhh, B);
        attn_kernel<<<B, 128>>>(B);
    }
    readout_kernel<<<(B + 7) / 8, 64>>>(fc1_w, fc1_b, fc2_w, fc2_b, y, B);
}

// round 14
// speedup vs baseline: 1.0177x; 1.0177x over previous
#include <cuda_runtime.h>
#include <cuda_bf16.h>
#include <cuda_fp16.h>
#include <math.h>

typedef unsigned long long ull;
typedef unsigned int uint;

#define MAXN 131072
#define MAXE 262144
#define MAXB 4096

// ---------------- device scratch ----------------
__device__ float g_msum[(size_t)MAXN * 64];
__device__ float g_cnt[MAXN];              // reused as attention e-buffer later
__device__ float g_out[(size_t)MAXN * 64];
__device__ float g_S[MAXB * 192];          // per graph: [0:128]=q_star, [128:192]=hl
__device__ float g_cl[MAXB * 64];
__device__ int   g_seg[MAXB + 1];
// edge GEMM: fp16 w_e2 (single), per-chunk smem images (16 chunks x 16384 B)
__device__ unsigned char g_W2hi[16 * 16384];
// GRU GEMM: Wg fp16 smem image [256 rows x 128 B], epilogue-friendly col order
__device__ unsigned char g_GBhi[32768];
__device__ float g_gbias[256];

// ---------------- helpers ----------------
__device__ __forceinline__ float fast_sigm(float x) {
    x = fminf(fmaxf(x, -30.0f), 30.0f);
    return __fdividef(1.0f, 1.0f + __expf(-x));
}
__device__ __forceinline__ float fast_tanh(float x) {
    x = fminf(fmaxf(x, -15.0f), 15.0f);
    float t = __expf(2.0f * x);
    return 1.0f - __fdividef(2.0f, 1.0f + t);
}
__device__ __forceinline__ uint smem_u32(const void* p) {
    uint a; asm("{ .reg .u64 t; cvta.to.shared.u64 t, %1; cvt.u32.u64 %0, t; }" : "=r"(a) : "l"(p));
    return a;
}
__device__ __forceinline__ void ldsm4(uint* r, uint addr) {
    asm volatile("ldmatrix.sync.aligned.m8n8.x4.shared.b16 {%0,%1,%2,%3}, [%4];"
        : "=r"(r[0]), "=r"(r[1]), "=r"(r[2]), "=r"(r[3]) : "r"(addr));
}
__device__ __forceinline__ void mma16816(float* d, const uint* a, const uint* b) {
    asm volatile("mma.sync.aligned.m16n8k16.row.col.f32.f16.f16.f32 "
        "{%0,%1,%2,%3}, {%4,%5,%6,%7}, {%8,%9}, {%0,%1,%2,%3};"
        : "+f"(d[0]), "+f"(d[1]), "+f"(d[2]), "+f"(d[3])
        : "r"(a[0]), "r"(a[1]), "r"(a[2]), "r"(a[3]), "r"(b[0]), "r"(b[1]));
}
__device__ __forceinline__ void cp16(uint dst, const void* src) {
    asm volatile("cp.async.ca.shared.global [%0], [%1], 16;" :: "r"(dst), "l"(src));
}
__device__ __forceinline__ void red2(float* p, float a, float b) {
    asm volatile("red.global.add.v2.f32 [%0], {%1, %2};" :: "l"(p), "f"(a), "f"(b) : "memory");
}

// ---------------- zero scratch ----------------
__global__ void zero_kernel(int N, int B) {
    int idx = blockIdx.x * blockDim.x + threadIdx.x;
    int stride = gridDim.x * blockDim.x;
    float4 z4 = make_float4(0.f, 0.f, 0.f, 0.f);
    int nm4 = N * 16;
    float4* m4 = (float4*)g_msum;
    for (int i = idx; i < nm4; i += stride) m4[i] = z4;
    for (int i = idx; i < N; i += stride) g_cnt[i] = 0.0f;
    int ns = B * 192;
    for (int i = idx; i < ns; i += stride) g_S[i] = 0.0f;
    int nc = B * 64;
    for (int i = idx; i < nc; i += stride) g_cl[i] = 0.0f;
}

// ---------------- segment offsets ----------------
__global__ void seg_kernel(const int* __restrict__ batch, int N, int B) {
    int b = blockIdx.x * blockDim.x + threadIdx.x;
    if (b > B) return;
    int lo = 0, hi = N;
    while (lo < hi) { int mid = (lo + hi) >> 1; if (batch[mid] < b) lo = mid + 1; else hi = mid; }
    g_seg[b] = lo;
}

// ---------------- merged prep ----------------
__device__ __forceinline__ void gru_col_decode(int c, int& j, int& gate) {
    int w = c >> 6, rem = c & 63;
    int half = rem >> 5, within = rem & 31;
    int tile = within >> 3, colin = within & 7;
    j = w * 16 + tile * 4 + (colin >> 1);
    gate = half * 2 + (colin & 1);
}

__global__ void prep_kernel(const float* __restrict__ w_e2,
                            const float* __restrict__ wih, const float* __restrict__ whh,
                            const float* __restrict__ bih, const float* __restrict__ bhh) {
    int bid = blockIdx.x;
    if (bid < 512) {
        int idx = bid * 256 + threadIdx.x;
        int m = idx >> 10, j = idx & 1023;     // m = k, j = d*64+h
        __half hi = __float2half_rn(w_e2[idx]);
        int nc = j >> 6, r = j & 63;
        int c = m >> 3;
        int off = r * 256 + ((c ^ (r & 7)) << 4) + (m & 7) * 2;
        *(__half*)(g_W2hi + nc * 16384 + off) = hi;
    } else {
        int idx = (bid - 512) * 256 + threadIdx.x;
        if (idx < 16384) {
            int c = idx >> 6, k = idx & 63;
            int j, gate;
            gru_col_decode(c, j, gate);
            float v;
            if (gate == 0)      v = wih[j * 64 + k] + whh[j * 64 + k];
            else if (gate == 1) v = wih[(64 + j) * 64 + k] + whh[(64 + j) * 64 + k];
            else if (gate == 2) v = wih[(128 + j) * 64 + k];
            else                v = whh[(128 + j) * 64 + k];
            __half hi = __float2half_rn(v);
            int off = c * 128 + (((k >> 3) ^ (c & 7)) << 4) + (k & 7) * 2;
            *(__half*)(g_GBhi + off) = hi;
        } else if (idx < 16640) {
            int c = idx - 16384;
            int j, gate;
            gru_col_decode(c, j, gate);
            float v;
            if (gate == 0)      v = bih[j] + bhh[j];
            else if (gate == 1) v = bih[64 + j] + bhh[64 + j];
            else if (gate == 2) v = bih[128 + j];
            else                v = bhh[128 + j];
            g_gbias[c] = v;
        }
    }
}

// ---------------- edge kernel: HMMA (single-pass fp16) — R12 form ----------------
#define O_A   0          // 32768 (A hid fp16, 128 rows x 256 B)
#define O_B   32768      // 2 x 16384 double buffer
#define O_XT  65536      // 8192  (xT [16][128] f32)
#define O_B2  73728      // 4096  (b_e2 1024 f32)
#define O_DST 77824      // 512
#define EK3_SMEM 78336

__global__ void __launch_bounds__(256, 2) edge_kernel3(
    const float* __restrict__ x, const float* __restrict__ edge_attr,
    const int* __restrict__ edge_index,
    const float* __restrict__ w_e1, const float* __restrict__ b_e1,
    const float* __restrict__ b_e2, int E)
{
    extern __shared__ char sm[];
    uint smb = smem_u32(sm);
    float* xT  = (float*)(sm + O_XT);
    float* b2S = (float*)(sm + O_B2);
    int*  dstS = (int*)(sm + O_DST);

    int t = threadIdx.x;
    int wid = t >> 5, lane = t & 31;
    int mw = wid & 3, nw = wid >> 2;
    int e0 = blockIdx.x * 128;

    // prefetch B chunk 0 (16 KB)
    {
        uint dst = smb + O_B + t * 16;
        const char* sh = (const char*)g_W2hi + t * 16;
        #pragma unroll
        for (int i = 0; i < 4; ++i) cp16(dst + i * 4096, sh + i * 4096);
        asm volatile("cp.async.commit_group;");
    }

    for (int i = t; i < 1024; i += 256) b2S[i] = b_e2[i];

    if (t < 128) {
        int e = e0 + t;
        int dd = -1;
        if (e < E) {
            int s = edge_index[e];
            dd = edge_index[E + e];
            const float4* xr = reinterpret_cast<const float4*>(x + (size_t)s * 16);
            #pragma unroll
            for (int q = 0; q < 4; ++q) {
                float4 v = xr[q];
                xT[(q * 4 + 0) * 128 + t] = v.x;
                xT[(q * 4 + 1) * 128 + t] = v.y;
                xT[(q * 4 + 2) * 128 + t] = v.z;
                xT[(q * 4 + 3) * 128 + t] = v.w;
            }
            atomicAdd(&g_cnt[dd], 1.0f);
        } else {
            #pragma unroll
            for (int q = 0; q < 16; ++q) xT[q * 128 + t] = 0.0f;
        }
        dstS[t] = dd;
    }

    // form A = fp16(hid)
    {
        int row = t >> 1;
        int cbase = (t & 1) * 8;
        int e = e0 + row;
        float ea0 = 0.f, ea1 = 0.f, ea2 = 0.f, ea3 = 0.f;
        if (e < E) {
            float4 ea = reinterpret_cast<const float4*>(edge_attr)[e];
            ea0 = ea.x; ea1 = ea.y; ea2 = ea.z; ea3 = ea.w;
        }
        #pragma unroll
        for (int c = cbase; c < cbase + 8; ++c) {
            uint h4[4];
            #pragma unroll
            for (int p = 0; p < 4; ++p) {
                int k0 = c * 8 + p * 2;
                float2 w0 = __ldg((const float2*)(w_e1 + k0));
                float2 w1 = __ldg((const float2*)(w_e1 + 128 + k0));
                float2 w2 = __ldg((const float2*)(w_e1 + 256 + k0));
                float2 w3 = __ldg((const float2*)(w_e1 + 384 + k0));
                float2 bb = __ldg((const float2*)(b_e1 + k0));
                float h0 = fmaf(ea3, w3.x, fmaf(ea2, w2.x, fmaf(ea1, w1.x, fmaf(ea0, w0.x, bb.x))));
                float h1 = fmaf(ea3, w3.y, fmaf(ea2, w2.y, fmaf(ea1, w1.y, fmaf(ea0, w0.y, bb.y))));
                __half2 hh = __floats2half2_rn(fmaxf(h0, 0.0f), fmaxf(h1, 0.0f));
                h4[p] = *reinterpret_cast<uint*>(&hh);
            }
            int off = row * 256 + ((c ^ (row & 7)) << 4);
            *(uint4*)(sm + O_A + off) = make_uint4(h4[0], h4[1], h4[2], h4[3]);
        }
    }

    float macc[2][4][4];
    #pragma unroll
    for (int a = 0; a < 2; ++a)
        #pragma unroll
        for (int b = 0; b < 4; ++b)
            #pragma unroll
            for (int r = 0; r < 4; ++r) macc[a][b][r] = 0.0f;

    uint smA = smb + O_A;

    for (int nc = 0; nc < 16; ++nc) {
        asm volatile("cp.async.wait_group 0;" ::: "memory");
        __syncthreads();
        uint smBbuf = smb + O_B + (nc & 1) * 16384;

        if (nc < 15) {
            uint dst = smb + O_B + ((nc + 1) & 1) * 16384 + t * 16;
            const char* sh = (const char*)g_W2hi + (nc + 1) * 16384 + t * 16;
            #pragma unroll
            for (int i = 0; i < 4; ++i) cp16(dst + i * 4096, sh + i * 4096);
            asm volatile("cp.async.commit_group;");
        }

        float dacc[2][4][4];
        #pragma unroll
        for (int a = 0; a < 2; ++a)
            #pragma unroll
            for (int b = 0; b < 4; ++b)
                #pragma unroll
                for (int r = 0; r < 4; ++r) dacc[a][b][r] = 0.0f;

        #pragma unroll
        for (int kt = 0; kt < 8; ++kt) {
            uint a0[4], a1[4];
            {
                int mi = lane >> 3;
                int arow = mw * 32 + (lane & 7) + (mi & 1) * 8;
                int ac = 2 * kt + (mi >> 1);
                uint addr = smA + arow * 256 + ((ac ^ (arow & 7)) << 4);
                ldsm4(a0, addr);
                ldsm4(a1, addr + 16 * 256);
            }
            uint bh[2][4];
            {
                int mi = lane >> 3;
                int nrow = nw * 32 + (mi >> 1) * 8 + (lane & 7);
                int bc = 2 * kt + (mi & 1);
                uint aH = smBbuf + nrow * 256 + ((bc ^ (nrow & 7)) << 4);
                ldsm4(bh[0], aH);
                ldsm4(bh[1], aH + 4096);
            }
            #pragma unroll
            for (int mt = 0; mt < 2; ++mt) {
                const uint* av = mt ? a1 : a0;
                #pragma unroll
                for (int ng = 0; ng < 2; ++ng) {
                    #pragma unroll
                    for (int s = 0; s < 2; ++s)
                        mma16816(dacc[mt][ng * 2 + s], av, &bh[ng][s * 2]);
                }
            }
        }

        // epilogue: msg += x[e,nc] * (D + b_e2)
        {
            int rb = mw * 32 + (lane >> 2);
            float xv00 = xT[nc * 128 + rb];
            float xv01 = xT[nc * 128 + rb + 8];
            float xv10 = xT[nc * 128 + rb + 16];
            float xv11 = xT[nc * 128 + rb + 24];
            #pragma unroll
            for (int mt = 0; mt < 2; ++mt) {
                float xa = mt ? xv10 : xv00;
                float xb = mt ? xv11 : xv01;
                #pragma unroll
                for (int nt = 0; nt < 4; ++nt) {
                    int col = nw * 32 + nt * 8 + 2 * (lane & 3);
                    float b0v = b2S[nc * 64 + col];
                    float b1v = b2S[nc * 64 + col + 1];
                    macc[mt][nt][0] = fmaf(xa, dacc[mt][nt][0] + b0v, macc[mt][nt][0]);
                    macc[mt][nt][1] = fmaf(xa, dacc[mt][nt][1] + b1v, macc[mt][nt][1]);
                    macc[mt][nt][2] = fmaf(xb, dacc[mt][nt][2] + b0v, macc[mt][nt][2]);
                    macc[mt][nt][3] = fmaf(xb, dacc[mt][nt][3] + b1v, macc[mt][nt][3]);
                }
            }
        }
    }

    // scatter: vectorized reductions (red.v2)
    #pragma unroll
    for (int mt = 0; mt < 2; ++mt) {
        #pragma unroll
        for (int half = 0; half < 2; ++half) {
            int row = mw * 32 + mt * 16 + (lane >> 2) + half * 8;
            int dd = dstS[row];
            if (dd < 0) continue;
            float* mr = g_msum + (size_t)dd * 64;
            #pragma unroll
            for (int nt = 0; nt < 4; ++nt) {
                int col = nw * 32 + nt * 8 + 2 * (lane & 3);
                red2(mr + col, macc[mt][nt][half * 2], macc[mt][nt][half * 2 + 1]);
            }
        }
    }
}

// ---------------- fused node + GRU x3 via HMMA (single-pass fp16, 2m x 4n grid) ----------------
#define G_HS   0        // 64 x 65 f32 = 16640 (col 64 = cnt)
#define G_AHI  16640    // 8192 (overlay: root 4096 + xS 4096 during node phase)
#define G_BHI  24832    // 32768
#define G_BIAS 57600    // 1024
#define GRU_SMEM 58624

__global__ void __launch_bounds__(256, 2) gru_node_kernel(
    const float* __restrict__ x, const float* __restrict__ root,
    const float* __restrict__ conv_bias, int N)
{
    extern __shared__ char sm2[];
    uint smb = smem_u32(sm2);
    float* hS    = (float*)(sm2 + G_HS);
    float* biasS = (float*)(sm2 + G_BIAS);
    float* rootS = (float*)(sm2 + G_AHI);          // node-phase overlay
    float* xS    = (float*)(sm2 + G_AHI + 4096);

    int t = threadIdx.x, wid = t >> 5, lane = t & 31;
    int n0 = blockIdx.x * 64;

    // stage B (32 KB) asynchronously — overlaps node phase
    {
        uint dh = smb + G_BHI + t * 16;
        const char* sh = (const char*)g_GBhi + t * 16;
        #pragma unroll
        for (int i = 0; i < 8; ++i) cp16(dh + i * 4096, sh + i * 4096);
        asm volatile("cp.async.commit_group;");
    }
    biasS[t] = g_gbias[t];

    // node-phase staging
    for (int i = t; i < 1024; i += 256) rootS[i] = root[i];
    for (int i = t; i < 1024; i += 256) {
        int r = i >> 4, d = i & 15;
        int n = n0 + r;
        xS[i] = (n < N) ? x[(size_t)n * 16 + d] : 0.0f;
    }
    if (t < 64) {
        int n = n0 + t;
        hS[t * 65 + 64] = (n < N) ? fmaxf(g_cnt[n], 1.0f) : 1.0f;
    }
    __syncthreads();

    // node update: hS = relu(msum/cnt + x@root + conv_bias)
    {
        float cbv = __ldg(conv_bias + (t & 63));
        #pragma unroll
        for (int j = 0; j < 16; ++j) {
            int idx = j * 256 + t;
            int r = idx >> 6, c = idx & 63;
            int n = n0 + r;
            float v = 0.0f;
            if (n < N) {
                float acc = cbv;
                const float* xr = xS + r * 16;
                #pragma unroll
                for (int d = 0; d < 16; ++d) acc = fmaf(xr[d], rootS[d * 64 + c], acc);
                v = fmaxf(g_msum[(size_t)n * 64 + c] / hS[r * 65 + 64] + acc, 0.0f);
            }
            hS[r * 65 + c] = v;
        }
    }
    asm volatile("cp.async.wait_group 0;" ::: "memory");
    __syncthreads();

    int mw = wid & 1, nh = wid >> 1;
    int mi = lane >> 3;
    uint smAhi = smb + G_AHI;
    uint smBh = smb + G_BHI;

    for (int step = 0; step < 3; ++step) {
        // convert hS -> fp16 A
        {
            int r = t >> 2, q = t & 3;
            const float* hr = hS + r * 65 + q * 16;
            #pragma unroll
            for (int c2 = 0; c2 < 2; ++c2) {
                uint hi4[4];
                #pragma unroll
                for (int p = 0; p < 4; ++p) {
                    __half2 hh = __floats2half2_rn(hr[c2 * 8 + p * 2], hr[c2 * 8 + p * 2 + 1]);
                    hi4[p] = *reinterpret_cast<uint*>(&hh);
                }
                int cc = q * 2 + c2;
                int off = r * 128 + ((cc ^ (r & 7)) << 4);
                *(uint4*)(sm2 + G_AHI + off) = make_uint4(hi4[0], hi4[1], hi4[2], hi4[3]);
            }
        }
        __syncthreads();

        float acc[16][4];
        #pragma unroll
        for (int i = 0; i < 16; ++i)
            #pragma unroll
            for (int j = 0; j < 4; ++j) acc[i][j] = 0.0f;

        #pragma unroll
        for (int kt = 0; kt < 4; ++kt) {
            uint a0[4], a1[4];
            {
                int arow = mw * 32 + (lane & 7) + (mi & 1) * 8;
                int ac = 2 * kt + (mi >> 1);
                uint aoff = (uint)(arow * 128 + ((ac ^ (arow & 7)) << 4));
                ldsm4(a0, smAhi + aoff);
                ldsm4(a1, smAhi + aoff + 16 * 128);
            }
            #pragma unroll
            for (int g2 = 0; g2 < 4; ++g2) {
                uint bh[4];
                int nrow = nh * 64 + g2 * 16 + (mi >> 1) * 8 + (lane & 7);
                int bc = 2 * kt + (mi & 1);
                uint boff = (uint)(nrow * 128 + ((bc ^ (nrow & 7)) << 4));
                ldsm4(bh, smBh + boff);
                mma16816(acc[0 * 8 + g2 * 2],     a0, bh);
                mma16816(acc[0 * 8 + g2 * 2 + 1], a0, bh + 2);
                mma16816(acc[1 * 8 + g2 * 2],     a1, bh);
                mma16816(acc[1 * 8 + g2 * 2 + 1], a1, bh + 2);
            }
        }
        __syncthreads();   // A reads complete before h' overwrite

        // gates -> h' (no shuffles: rz tiles 0..3 pair with inhn tiles 4..7, same lane/j)
        {
            int qj = lane & 3;
            int rb = lane >> 2;
            #pragma unroll
            for (int mt = 0; mt < 2; ++mt) {
                #pragma unroll
                for (int tp = 0; tp < 4; ++tp) {
                    float* aRZ = acc[mt * 8 + tp];
                    float* aNH = acc[mt * 8 + tp + 4];
                    int cb = nh * 64 + tp * 8 + 2 * qj;
                    float br = biasS[cb],      bz = biasS[cb + 1];
                    float bi = biasS[cb + 32], bn = biasS[cb + 33];
                    int j = nh * 16 + tp * 4 + qj;
                    int ra = mw * 32 + mt * 16 + rb;
                    {
                        float r = fast_sigm(aRZ[0] + br), z = fast_sigm(aRZ[1] + bz);
                        float nv = fast_tanh((aNH[0] + bi) + r * (aNH[1] + bn));
                        float hold = hS[ra * 65 + j];
                        hS[ra * 65 + j] = (1.0f - z) * nv + z * hold;
                    }
                    {
                        float r = fast_sigm(aRZ[2] + br), z = fast_sigm(aRZ[3] + bz);
                        float nv = fast_tanh((aNH[2] + bi) + r * (aNH[3] + bn));
                        float hold = hS[(ra + 8) * 65 + j];
                        hS[(ra + 8) * 65 + j] = (1.0f - z) * nv + z * hold;
                    }
                }
            }
        }
        __syncthreads();
    }

    // coalesced writeback
    #pragma unroll
    for (int j = 0; j < 16; ++j) {
        int idx = j * 256 + t;
        int r = idx >> 6, c = idx & 63;
        int n = n0 + r;
        if (n < N) g_out[(size_t)n * 64 + c] = hS[r * 65 + c];
    }
}

// ---------------- Set2Set LSTM step ----------------
__global__ void __launch_bounds__(256) lstm_kernel(
    const float* __restrict__ wih, const float* __restrict__ whh,
    const float* __restrict__ bih, const float* __restrict__ bhh, int B)
{
    __shared__ float wst[256 * 33];
    __shared__ float qsm[8 * 128];
    __shared__ float hsm[8 * 64];
    __shared__ float gsm[8 * 256];
    int t = threadIdx.x;
    int b0 = blockIdx.x * 8;

    for (int i = t; i < 8 * 128; i += 256) {
        int g = i >> 7, k = i & 127;
        qsm[i] = (b0 + g < B) ? g_S[(b0 + g) * 192 + k] : 0.0f;
    }
    for (int i = t; i < 8 * 64; i += 256) {
        int g = i >> 6, k = i & 63;
        hsm[i] = (b0 + g < B) ? g_S[(b0 + g) * 192 + 128 + k] : 0.0f;
    }

    float acc[8];
    float bsum = bih[t] + bhh[t];
    #pragma unroll
    for (int g = 0; g < 8; ++g) acc[g] = bsum;

    for (int c = 0; c < 4; ++c) {
        __syncthreads();
        for (int i = t; i < 8192; i += 256) {
            int j = i >> 5, kk = i & 31;
            wst[j * 33 + kk] = wih[j * 128 + c * 32 + kk];
        }
        __syncthreads();
        #pragma unroll 8
        for (int kk = 0; kk < 32; ++kk) {
            float w = wst[t * 33 + kk];
            #pragma unroll
            for (int g = 0; g < 8; ++g)
                acc[g] = fmaf(w, qsm[g * 128 + c * 32 + kk], acc[g]);
        }
    }
    for (int c = 0; c < 2; ++c) {
        __syncthreads();
        for (int i = t; i < 8192; i += 256) {
            int j = i >> 5, kk = i & 31;
            wst[j * 33 + kk] = whh[j * 64 + c * 32 + kk];
        }
        __syncthreads();
        #pragma unroll 8
        for (int kk = 0; kk < 32; ++kk) {
            float w = wst[t * 33 + kk];
            #pragma unroll
            for (int g = 0; g < 8; ++g)
                acc[g] = fmaf(w, hsm[g * 64 + c * 32 + kk], acc[g]);
        }
    }

    #pragma unroll
    for (int g = 0; g < 8; ++g) gsm[g * 256 + t] = acc[g];
    __syncthreads();

    for (int i = t; i < 8 * 64; i += 256) {
        int g = i >> 6, hh = i & 63;
        int b = b0 + g;
        if (b >= B) continue;
        float ig = fast_sigm(gsm[g * 256 + hh]);
        float fg = fast_sigm(gsm[g * 256 + 64 + hh]);
        float gg = fast_tanh(gsm[g * 256 + 128 + hh]);
        float og = fast_sigm(gsm[g * 256 + 192 + hh]);
        float cnew = fg * g_cl[b * 64 + hh] + ig * gg;
        g_cl[b * 64 + hh] = cnew;
        g_S[b * 192 + 128 + hh] = og * fast_tanh(cnew);
    }
}

// ---------------- Set2Set attention step (256 threads / graph) ----------------
__global__ void __launch_bounds__(256) attn_kernel(int B)
{
    __shared__ float qs[64];
    __shared__ float wm[8], ws[8];
    __shared__ float rgS[3][64];
    int t = threadIdx.x, b = blockIdx.x;
    if (t < 64) qs[t] = g_S[b * 192 + 128 + t];
    __syncthreads();
    int n0 = g_seg[b], n1 = g_seg[b + 1];
    int w = t >> 5, lid = t & 31;

    // pass 1: e[n] = dot(out[n], q), 8 warps interleaved; e-buffer = g_cnt
    float mr = -1e30f, sr = 0.0f;
    for (int n = n0 + w; n < n1; n += 8) {
        const float* orow = g_out + (size_t)n * 64;
        float p = orow[lid] * qs[lid] + orow[32 + lid] * qs[32 + lid];
        #pragma unroll
        for (int off = 16; off; off >>= 1) p += __shfl_xor_sync(0xffffffffu, p, off);
        if (lid == 0) g_cnt[n] = p;
        if (p > mr) { sr *= __expf(mr - p); mr = p; }
        sr += __expf(p - mr);
    }
    if (lid == 0) { wm[w] = mr; ws[w] = sr; }
    __syncthreads();
    float m = wm[0];
    #pragma unroll
    for (int i = 1; i < 8; ++i) m = fmaxf(m, wm[i]);
    float denom = 0.0f;
    #pragma unroll
    for (int i = 0; i < 8; ++i) denom += ws[i] * __expf(wm[i] - m);

    // pass 2: four node-quarters
    int col = t & 63, qtr = t >> 6;
    float rg = 0.0f;
    for (int n = n0 + qtr; n < n1; n += 4)
        rg = fmaf(__expf(g_cnt[n] - m), g_out[(size_t)n * 64 + col], rg);
    if (qtr) rgS[qtr - 1][col] = rg;
    __syncthreads();
    if (!qtr) {
        rg += rgS[0][col] + rgS[1][col] + rgS[2][col];
        if (n1 > n0) rg /= denom;
        g_S[b * 192 + col]      = qs[col];
        g_S[b * 192 + 64 + col] = rg;
    }
}

// ---------------- readout ----------------
__global__ void __launch_bounds__(64) readout_kernel(
    const float* __restrict__ fc1_w, const float* __restrict__ fc1_b,
    const float* __restrict__ fc2_w, const float* __restrict__ fc2_b,
    float* __restrict__ y, int B)
{
    __shared__ float qsm[8 * 128];
    __shared__ float red[2];
    int t = threadIdx.x;
    int b0 = blockIdx.x * 8;
    for (int i = t; i < 1024; i += 64) {
        int g = i >> 7, k = i & 127;
        qsm[i] = (b0 + g < B) ? g_S[(b0 + g) * 192 + k] : 0.0f;
    }
    __syncthreads();
    float w2 = fc2_w[t];
    float b1 = fc1_b[t];
    for (int g = 0; g < 8; ++g) {
        float a = b1;
        #pragma unroll 8
        for (int k = 0; k < 128; ++k) a = fmaf(qsm[g * 128 + k], fc1_w[k * 64 + t], a);
        a = fmaxf(a, 0.0f);
        float p = a * w2;
        #pragma unroll
        for (int off = 16; off; off >>= 1) p += __shfl_xor_sync(0xffffffffu, p, off);
        if ((t & 31) == 0) red[t >> 5] = p;
        __syncthreads();
        if (t == 0 && b0 + g < B) y[b0 + g] = red[0] + red[1] + fc2_b[0];
        __syncthreads();
    }
}

// ---------------- launch ----------------
extern "C" void kernel_launch(void* const* d_in, const int* in_sizes, int n_in,
                              void* d_out, int out_size)
{
    const float* x         = (const float*)d_in[0];
    const float* edge_attr = (const float*)d_in[1];
    const int*   edge_index= (const int*)  d_in[2];
    const int*   batch     = (const int*)  d_in[3];
    const float* w_e1      = (const float*)d_in[4];
    const float* b_e1      = (const float*)d_in[5];
    const float* w_e2      = (const float*)d_in[6];
    const float* b_e2      = (const float*)d_in[7];
    const float* root      = (const float*)d_in[8];
    const float* conv_bias = (const float*)d_in[9];
    const float* gru_wih   = (const float*)d_in[10];
    const float* gru_whh   = (const float*)d_in[11];
    const float* gru_bih   = (const float*)d_in[12];
    const float* gru_bhh   = (const float*)d_in[13];
    const float* lstm_wih  = (const float*)d_in[14];
    const float* lstm_whh  = (const float*)d_in[15];
    const float* lstm_bih  = (const float*)d_in[16];
    const float* lstm_bhh  = (const float*)d_in[17];
    const float* fc1_w     = (const float*)d_in[18];
    const float* fc1_b     = (const float*)d_in[19];
    const float* fc2_w     = (const float*)d_in[20];
    const float* fc2_b     = (const float*)d_in[21];
    float* y = (float*)d_out;

    int N = in_sizes[0] / 16;
    int E = in_sizes[1] / 4;
    int B = out_size;

    static int smem_set = 0;
    if (!smem_set) {
        cudaFuncSetAttribute(edge_kernel3, cudaFuncAttributeMaxDynamicSharedMemorySize, EK3_SMEM);
        cudaFuncSetAttribute(gru_node_kernel, cudaFuncAttributeMaxDynamicSharedMemorySize, GRU_SMEM);
        smem_set = 1;
    }

    // edge_kernel3 is the 4th launch (ncu capture window) — verify the revert.
    prep_kernel<<<577, 256>>>(w_e2, gru_wih, gru_whh, gru_bih, gru_bhh);
    zero_kernel<<<1024, 256>>>(N, B);
    seg_kernel<<<(B + 1 + 127) / 128, 128>>>(batch, N, B);
    edge_kernel3<<<(E + 127) / 128, 256, EK3_SMEM>>>(x, edge_attr, edge_index, w_e1, b_e1, b_e2, E);
    gru_node_kernel<<<(N + 63) / 64, 256, GRU_SMEM>>>(x, root, conv_bias, N);
    for (int i = 0; i < 3; ++i) {
        lstm_kernel<<<(B + 7) / 8, 256>>>(lstm_wih, lstm_whh, lstm_bih, lstm_bhh, B);
        attn_kernel<<<B, 256>>>(B);
    }
    readout_kernel<<<(B + 7) / 8, 64>>>(fc1_w, fc1_b, fc2_w, fc2_b, y, B);
}

// round 15
// speedup vs baseline: 1.1122x; 1.0928x over previous
#include <cuda_runtime.h>
#include <cuda_bf16.h>
#include <cuda_fp16.h>
#include <math.h>

typedef unsigned long long ull;
typedef unsigned int uint;

#define MAXN 131072
#define MAXE 262144
#define MAXB 4096

// ---------------- device scratch ----------------
__device__ float g_msum[(size_t)MAXN * 64];
__device__ float g_cnt[MAXN];              // reused as attention e-buffer later
__device__ float g_out[(size_t)MAXN * 64];
__device__ float g_S[MAXB * 192];          // per graph: [0:128]=q_star, [128:192]=hl
__device__ float g_cl[MAXB * 64];
__device__ int   g_seg[MAXB + 1];
// edge GEMM: fp16 w_e2 (single), per-chunk smem images (16 chunks x 16384 B)
__device__ unsigned char g_W2hi[16 * 16384];
// GRU GEMM: Wg fp16 smem image [256 rows x 128 B], epilogue-friendly col order
__device__ unsigned char g_GBhi[32768];
__device__ float g_gbias[256];
// LSTM combined weights: row j (gate 0..255), col k (0..127): k<64 -> wih[:, :64]+whh; k>=64 -> wih[:, 64:]
__device__ float g_LW[256 * 128];

// ---------------- helpers ----------------
__device__ __forceinline__ float fast_sigm(float x) {
    x = fminf(fmaxf(x, -30.0f), 30.0f);
    return __fdividef(1.0f, 1.0f + __expf(-x));
}
__device__ __forceinline__ float fast_tanh(float x) {
    x = fminf(fmaxf(x, -15.0f), 15.0f);
    float t = __expf(2.0f * x);
    return 1.0f - __fdividef(2.0f, 1.0f + t);
}
__device__ __forceinline__ uint smem_u32(const void* p) {
    uint a; asm("{ .reg .u64 t; cvta.to.shared.u64 t, %1; cvt.u32.u64 %0, t; }" : "=r"(a) : "l"(p));
    return a;
}
__device__ __forceinline__ void ldsm4(uint* r, uint addr) {
    asm volatile("ldmatrix.sync.aligned.m8n8.x4.shared.b16 {%0,%1,%2,%3}, [%4];"
        : "=r"(r[0]), "=r"(r[1]), "=r"(r[2]), "=r"(r[3]) : "r"(addr));
}
__device__ __forceinline__ void mma16816(float* d, const uint* a, const uint* b) {
    asm volatile("mma.sync.aligned.m16n8k16.row.col.f32.f16.f16.f32 "
        "{%0,%1,%2,%3}, {%4,%5,%6,%7}, {%8,%9}, {%0,%1,%2,%3};"
        : "+f"(d[0]), "+f"(d[1]), "+f"(d[2]), "+f"(d[3])
        : "r"(a[0]), "r"(a[1]), "r"(a[2]), "r"(a[3]), "r"(b[0]), "r"(b[1]));
}
__device__ __forceinline__ void cp16(uint dst, const void* src) {
    asm volatile("cp.async.ca.shared.global [%0], [%1], 16;" :: "r"(dst), "l"(src));
}
__device__ __forceinline__ void red2(float* p, float a, float b) {
    asm volatile("red.global.add.v2.f32 [%0], {%1, %2};" :: "l"(p), "f"(a), "f"(b) : "memory");
}

// ---------------- merged setup: w2 prep + gru prep + lstm prep + zero + seg ----------------
__device__ __forceinline__ void gru_col_decode(int c, int& j, int& gate) {
    int w = c >> 6, rem = c & 63;
    int half = rem >> 5, within = rem & 31;
    int tile = within >> 3, colin = within & 7;
    j = w * 16 + tile * 4 + (colin >> 1);
    gate = half * 2 + (colin & 1);
}

#define SB_W2   0        // [0, 512)   w_e2 images
#define SB_GRU  512      // [512, 577) gru images + bias
#define SB_LW   577      // [577, 705) lstm combined weights
#define SB_ZERO 705      // [705, 1729) zero scratch (1024 blocks, grid-stride)
#define SB_SEG  1729     // [1729, 1746) segment offsets
#define SETUP_BLOCKS 1746

__global__ void setup_kernel(const float* __restrict__ w_e2,
                             const float* __restrict__ gwih, const float* __restrict__ gwhh,
                             const float* __restrict__ gbih, const float* __restrict__ gbhh,
                             const float* __restrict__ lwih, const float* __restrict__ lwhh,
                             const int* __restrict__ batch, int N, int B)
{
    int bid = blockIdx.x;
    int t = threadIdx.x;
    if (bid < SB_GRU) {
        int idx = bid * 256 + t;
        int m = idx >> 10, j = idx & 1023;     // m = k, j = d*64+h
        __half hi = __float2half_rn(w_e2[idx]);
        int nc = j >> 6, r = j & 63;
        int c = m >> 3;
        int off = r * 256 + ((c ^ (r & 7)) << 4) + (m & 7) * 2;
        *(__half*)(g_W2hi + nc * 16384 + off) = hi;
    } else if (bid < SB_LW) {
        int idx = (bid - SB_GRU) * 256 + t;
        if (idx < 16384) {
            int c = idx >> 6, k = idx & 63;
            int j, gate;
            gru_col_decode(c, j, gate);
            float v;
            if (gate == 0)      v = gwih[j * 64 + k] + gwhh[j * 64 + k];
            else if (gate == 1) v = gwih[(64 + j) * 64 + k] + gwhh[(64 + j) * 64 + k];
            else if (gate == 2) v = gwih[(128 + j) * 64 + k];
            else                v = gwhh[(128 + j) * 64 + k];
            __half hi = __float2half_rn(v);
            int off = c * 128 + (((k >> 3) ^ (c & 7)) << 4) + (k & 7) * 2;
            *(__half*)(g_GBhi + off) = hi;
        } else if (idx < 16640) {
            int c = idx - 16384;
            int j, gate;
            gru_col_decode(c, j, gate);
            float v;
            if (gate == 0)      v = gbih[j] + gbhh[j];
            else if (gate == 1) v = gbih[64 + j] + gbhh[64 + j];
            else if (gate == 2) v = gbih[128 + j];
            else                v = gbhh[128 + j];
            g_gbias[c] = v;
        }
    } else if (bid < SB_ZERO) {
        int idx = (bid - SB_LW) * 256 + t;   // 0 .. 32767
        int j = idx >> 7, k = idx & 127;
        g_LW[idx] = (k < 64) ? (lwih[j * 128 + k] + lwhh[j * 64 + k]) : lwih[j * 128 + k];
    } else if (bid < SB_SEG) {
        int idx = (bid - SB_ZERO) * 256 + t;
        int stride = 1024 * 256;
        float4 z4 = make_float4(0.f, 0.f, 0.f, 0.f);
        int nm4 = N * 16;
        float4* m4 = (float4*)g_msum;
        for (int i = idx; i < nm4; i += stride) m4[i] = z4;
        for (int i = idx; i < N; i += stride) g_cnt[i] = 0.0f;
        int ns = B * 192;
        for (int i = idx; i < ns; i += stride) g_S[i] = 0.0f;
        int nc = B * 64;
        for (int i = idx; i < nc; i += stride) g_cl[i] = 0.0f;
    } else {
        int b = (bid - SB_SEG) * 256 + t;
        if (b > B) return;
        int lo = 0, hi = N;
        while (lo < hi) { int mid = (lo + hi) >> 1; if (batch[mid] < b) lo = mid + 1; else hi = mid; }
        g_seg[b] = lo;
    }
}

// ---------------- edge kernel: HMMA (single-pass fp16) — R12 form ----------------
#define O_A   0          // 32768 (A hid fp16, 128 rows x 256 B)
#define O_B   32768      // 2 x 16384 double buffer
#define O_XT  65536      // 8192  (xT [16][128] f32)
#define O_B2  73728      // 4096  (b_e2 1024 f32)
#define O_DST 77824      // 512
#define EK3_SMEM 78336

__global__ void __launch_bounds__(256, 2) edge_kernel3(
    const float* __restrict__ x, const float* __restrict__ edge_attr,
    const int* __restrict__ edge_index,
    const float* __restrict__ w_e1, const float* __restrict__ b_e1,
    const float* __restrict__ b_e2, int E)
{
    extern __shared__ char sm[];
    uint smb = smem_u32(sm);
    float* xT  = (float*)(sm + O_XT);
    float* b2S = (float*)(sm + O_B2);
    int*  dstS = (int*)(sm + O_DST);

    int t = threadIdx.x;
    int wid = t >> 5, lane = t & 31;
    int mw = wid & 3, nw = wid >> 2;
    int e0 = blockIdx.x * 128;

    // prefetch B chunk 0 (16 KB)
    {
        uint dst = smb + O_B + t * 16;
        const char* sh = (const char*)g_W2hi + t * 16;
        #pragma unroll
        for (int i = 0; i < 4; ++i) cp16(dst + i * 4096, sh + i * 4096);
        asm volatile("cp.async.commit_group;");
    }

    for (int i = t; i < 1024; i += 256) b2S[i] = b_e2[i];

    if (t < 128) {
        int e = e0 + t;
        int dd = -1;
        if (e < E) {
            int s = edge_index[e];
            dd = edge_index[E + e];
            const float4* xr = reinterpret_cast<const float4*>(x + (size_t)s * 16);
            #pragma unroll
            for (int q = 0; q < 4; ++q) {
                float4 v = xr[q];
                xT[(q * 4 + 0) * 128 + t] = v.x;
                xT[(q * 4 + 1) * 128 + t] = v.y;
                xT[(q * 4 + 2) * 128 + t] = v.z;
                xT[(q * 4 + 3) * 128 + t] = v.w;
            }
            atomicAdd(&g_cnt[dd], 1.0f);
        } else {
            #pragma unroll
            for (int q = 0; q < 16; ++q) xT[q * 128 + t] = 0.0f;
        }
        dstS[t] = dd;
    }

    // form A = fp16(hid)
    {
        int row = t >> 1;
        int cbase = (t & 1) * 8;
        int e = e0 + row;
        float ea0 = 0.f, ea1 = 0.f, ea2 = 0.f, ea3 = 0.f;
        if (e < E) {
            float4 ea = reinterpret_cast<const float4*>(edge_attr)[e];
            ea0 = ea.x; ea1 = ea.y; ea2 = ea.z; ea3 = ea.w;
        }
        #pragma unroll
        for (int c = cbase; c < cbase + 8; ++c) {
            uint h4[4];
            #pragma unroll
            for (int p = 0; p < 4; ++p) {
                int k0 = c * 8 + p * 2;
                float2 w0 = __ldg((const float2*)(w_e1 + k0));
                float2 w1 = __ldg((const float2*)(w_e1 + 128 + k0));
                float2 w2 = __ldg((const float2*)(w_e1 + 256 + k0));
                float2 w3 = __ldg((const float2*)(w_e1 + 384 + k0));
                float2 bb = __ldg((const float2*)(b_e1 + k0));
                float h0 = fmaf(ea3, w3.x, fmaf(ea2, w2.x, fmaf(ea1, w1.x, fmaf(ea0, w0.x, bb.x))));
                float h1 = fmaf(ea3, w3.y, fmaf(ea2, w2.y, fmaf(ea1, w1.y, fmaf(ea0, w0.y, bb.y))));
                __half2 hh = __floats2half2_rn(fmaxf(h0, 0.0f), fmaxf(h1, 0.0f));
                h4[p] = *reinterpret_cast<uint*>(&hh);
            }
            int off = row * 256 + ((c ^ (row & 7)) << 4);
            *(uint4*)(sm + O_A + off) = make_uint4(h4[0], h4[1], h4[2], h4[3]);
        }
    }

    float macc[2][4][4];
    #pragma unroll
    for (int a = 0; a < 2; ++a)
        #pragma unroll
        for (int b = 0; b < 4; ++b)
            #pragma unroll
            for (int r = 0; r < 4; ++r) macc[a][b][r] = 0.0f;

    uint smA = smb + O_A;

    for (int nc = 0; nc < 16; ++nc) {
        asm volatile("cp.async.wait_group 0;" ::: "memory");
        __syncthreads();
        uint smBbuf = smb + O_B + (nc & 1) * 16384;

        if (nc < 15) {
            uint dst = smb + O_B + ((nc + 1) & 1) * 16384 + t * 16;
            const char* sh = (const char*)g_W2hi + (nc + 1) * 16384 + t * 16;
            #pragma unroll
            for (int i = 0; i < 4; ++i) cp16(dst + i * 4096, sh + i * 4096);
            asm volatile("cp.async.commit_group;");
        }

        float dacc[2][4][4];
        #pragma unroll
        for (int a = 0; a < 2; ++a)
            #pragma unroll
            for (int b = 0; b < 4; ++b)
                #pragma unroll
                for (int r = 0; r < 4; ++r) dacc[a][b][r] = 0.0f;

        #pragma unroll
        for (int kt = 0; kt < 8; ++kt) {
            uint a0[4], a1[4];
            {
                int mi = lane >> 3;
                int arow = mw * 32 + (lane & 7) + (mi & 1) * 8;
                int ac = 2 * kt + (mi >> 1);
                uint addr = smA + arow * 256 + ((ac ^ (arow & 7)) << 4);
                ldsm4(a0, addr);
                ldsm4(a1, addr + 16 * 256);
            }
            uint bh[2][4];
            {
                int mi = lane >> 3;
                int nrow = nw * 32 + (mi >> 1) * 8 + (lane & 7);
                int bc = 2 * kt + (mi & 1);
                uint aH = smBbuf + nrow * 256 + ((bc ^ (nrow & 7)) << 4);
                ldsm4(bh[0], aH);
                ldsm4(bh[1], aH + 4096);
            }
            #pragma unroll
            for (int mt = 0; mt < 2; ++mt) {
                const uint* av = mt ? a1 : a0;
                #pragma unroll
                for (int ng = 0; ng < 2; ++ng) {
                    #pragma unroll
                    for (int s = 0; s < 2; ++s)
                        mma16816(dacc[mt][ng * 2 + s], av, &bh[ng][s * 2]);
                }
            }
        }

        // epilogue: msg += x[e,nc] * (D + b_e2)
        {
            int rb = mw * 32 + (lane >> 2);
            float xv00 = xT[nc * 128 + rb];
            float xv01 = xT[nc * 128 + rb + 8];
            float xv10 = xT[nc * 128 + rb + 16];
            float xv11 = xT[nc * 128 + rb + 24];
            #pragma unroll
            for (int mt = 0; mt < 2; ++mt) {
                float xa = mt ? xv10 : xv00;
                float xb = mt ? xv11 : xv01;
                #pragma unroll
                for (int nt = 0; nt < 4; ++nt) {
                    int col = nw * 32 + nt * 8 + 2 * (lane & 3);
                    float b0v = b2S[nc * 64 + col];
                    float b1v = b2S[nc * 64 + col + 1];
                    macc[mt][nt][0] = fmaf(xa, dacc[mt][nt][0] + b0v, macc[mt][nt][0]);
                    macc[mt][nt][1] = fmaf(xa, dacc[mt][nt][1] + b1v, macc[mt][nt][1]);
                    macc[mt][nt][2] = fmaf(xb, dacc[mt][nt][2] + b0v, macc[mt][nt][2]);
                    macc[mt][nt][3] = fmaf(xb, dacc[mt][nt][3] + b1v, macc[mt][nt][3]);
                }
            }
        }
    }

    // scatter: vectorized reductions (red.v2)
    #pragma unroll
    for (int mt = 0; mt < 2; ++mt) {
        #pragma unroll
        for (int half = 0; half < 2; ++half) {
            int row = mw * 32 + mt * 16 + (lane >> 2) + half * 8;
            int dd = dstS[row];
            if (dd < 0) continue;
            float* mr = g_msum + (size_t)dd * 64;
            #pragma unroll
            for (int nt = 0; nt < 4; ++nt) {
                int col = nw * 32 + nt * 8 + 2 * (lane & 3);
                red2(mr + col, macc[mt][nt][half * 2], macc[mt][nt][half * 2 + 1]);
            }
        }
    }
}

// ---------------- fused node + GRU x3 via HMMA (single-pass fp16, 2m x 4n grid) ----------------
#define G_HS   0        // 64 x 65 f32 = 16640 (col 64 = cnt)
#define G_AHI  16640    // 8192 (overlay: root 4096 + xS 4096 during node phase)
#define G_BHI  24832    // 32768
#define G_BIAS 57600    // 1024
#define GRU_SMEM 58624

__global__ void __launch_bounds__(256, 2) gru_node_kernel(
    const float* __restrict__ x, const float* __restrict__ root,
    const float* __restrict__ conv_bias, int N)
{
    extern __shared__ char sm2[];
    uint smb = smem_u32(sm2);
    float* hS    = (float*)(sm2 + G_HS);
    float* biasS = (float*)(sm2 + G_BIAS);
    float* rootS = (float*)(sm2 + G_AHI);          // node-phase overlay
    float* xS    = (float*)(sm2 + G_AHI + 4096);

    int t = threadIdx.x, wid = t >> 5, lane = t & 31;
    int n0 = blockIdx.x * 64;

    // stage B (32 KB) asynchronously — overlaps node phase
    {
        uint dh = smb + G_BHI + t * 16;
        const char* sh = (const char*)g_GBhi + t * 16;
        #pragma unroll
        for (int i = 0; i < 8; ++i) cp16(dh + i * 4096, sh + i * 4096);
        asm volatile("cp.async.commit_group;");
    }
    biasS[t] = g_gbias[t];

    // node-phase staging
    for (int i = t; i < 1024; i += 256) rootS[i] = root[i];
    for (int i = t; i < 1024; i += 256) {
        int r = i >> 4, d = i & 15;
        int n = n0 + r;
        xS[i] = (n < N) ? x[(size_t)n * 16 + d] : 0.0f;
    }
    if (t < 64) {
        int n = n0 + t;
        hS[t * 65 + 64] = (n < N) ? fmaxf(g_cnt[n], 1.0f) : 1.0f;
    }
    __syncthreads();

    // node update: hS = relu(msum/cnt + x@root + conv_bias)
    {
        float cbv = __ldg(conv_bias + (t & 63));
        #pragma unroll
        for (int j = 0; j < 16; ++j) {
            int idx = j * 256 + t;
            int r = idx >> 6, c = idx & 63;
            int n = n0 + r;
            float v = 0.0f;
            if (n < N) {
                float acc = cbv;
                const float* xr = xS + r * 16;
                #pragma unroll
                for (int d = 0; d < 16; ++d) acc = fmaf(xr[d], rootS[d * 64 + c], acc);
                v = fmaxf(g_msum[(size_t)n * 64 + c] / hS[r * 65 + 64] + acc, 0.0f);
            }
            hS[r * 65 + c] = v;
        }
    }
    asm volatile("cp.async.wait_group 0;" ::: "memory");
    __syncthreads();

    int mw = wid & 1, nh = wid >> 1;
    int mi = lane >> 3;
    uint smAhi = smb + G_AHI;
    uint smBh = smb + G_BHI;

    for (int step = 0; step < 3; ++step) {
        // convert hS -> fp16 A
        {
            int r = t >> 2, q = t & 3;
            const float* hr = hS + r * 65 + q * 16;
            #pragma unroll
            for (int c2 = 0; c2 < 2; ++c2) {
                uint hi4[4];
                #pragma unroll
                for (int p = 0; p < 4; ++p) {
                    __half2 hh = __floats2half2_rn(hr[c2 * 8 + p * 2], hr[c2 * 8 + p * 2 + 1]);
                    hi4[p] = *reinterpret_cast<uint*>(&hh);
                }
                int cc = q * 2 + c2;
                int off = r * 128 + ((cc ^ (r & 7)) << 4);
                *(uint4*)(sm2 + G_AHI + off) = make_uint4(hi4[0], hi4[1], hi4[2], hi4[3]);
            }
        }
        __syncthreads();

        float acc[16][4];
        #pragma unroll
        for (int i = 0; i < 16; ++i)
            #pragma unroll
            for (int j = 0; j < 4; ++j) acc[i][j] = 0.0f;

        #pragma unroll
        for (int kt = 0; kt < 4; ++kt) {
            uint a0[4], a1[4];
            {
                int arow = mw * 32 + (lane & 7) + (mi & 1) * 8;
                int ac = 2 * kt + (mi >> 1);
                uint aoff = (uint)(arow * 128 + ((ac ^ (arow & 7)) << 4));
                ldsm4(a0, smAhi + aoff);
                ldsm4(a1, smAhi + aoff + 16 * 128);
            }
            #pragma unroll
            for (int g2 = 0; g2 < 4; ++g2) {
                uint bh[4];
                int nrow = nh * 64 + g2 * 16 + (mi >> 1) * 8 + (lane & 7);
                int bc = 2 * kt + (mi & 1);
                uint boff = (uint)(nrow * 128 + ((bc ^ (nrow & 7)) << 4));
                ldsm4(bh, smBh + boff);
                mma16816(acc[0 * 8 + g2 * 2],     a0, bh);
                mma16816(acc[0 * 8 + g2 * 2 + 1], a0, bh + 2);
                mma16816(acc[1 * 8 + g2 * 2],     a1, bh);
                mma16816(acc[1 * 8 + g2 * 2 + 1], a1, bh + 2);
            }
        }
        __syncthreads();   // A reads complete before h' overwrite

        // gates -> h' (no shuffles: rz tiles 0..3 pair with inhn tiles 4..7, same lane/j)
        {
            int qj = lane & 3;
            int rb = lane >> 2;
            #pragma unroll
            for (int mt = 0; mt < 2; ++mt) {
                #pragma unroll
                for (int tp = 0; tp < 4; ++tp) {
                    float* aRZ = acc[mt * 8 + tp];
                    float* aNH = acc[mt * 8 + tp + 4];
                    int cb = nh * 64 + tp * 8 + 2 * qj;
                    float br = biasS[cb],      bz = biasS[cb + 1];
                    float bi = biasS[cb + 32], bn = biasS[cb + 33];
                    int j = nh * 16 + tp * 4 + qj;
                    int ra = mw * 32 + mt * 16 + rb;
                    {
                        float r = fast_sigm(aRZ[0] + br), z = fast_sigm(aRZ[1] + bz);
                        float nv = fast_tanh((aNH[0] + bi) + r * (aNH[1] + bn));
                        float hold = hS[ra * 65 + j];
                        hS[ra * 65 + j] = (1.0f - z) * nv + z * hold;
                    }
                    {
                        float r = fast_sigm(aRZ[2] + br), z = fast_sigm(aRZ[3] + bz);
                        float nv = fast_tanh((aNH[2] + bi) + r * (aNH[3] + bn));
                        float hold = hS[(ra + 8) * 65 + j];
                        hS[(ra + 8) * 65 + j] = (1.0f - z) * nv + z * hold;
                    }
                }
            }
        }
        __syncthreads();
    }

    // coalesced writeback
    #pragma unroll
    for (int j = 0; j < 16; ++j) {
        int idx = j * 256 + t;
        int r = idx >> 6, c = idx & 63;
        int n = n0 + r;
        if (n < N) g_out[(size_t)n * 64 + c] = hS[r * 65 + c];
    }
}

// ---------------- Set2Set LSTM step (K=128 via q_star[0:64]==hl identity) ----------------
__global__ void __launch_bounds__(256) lstm_kernel(
    const float* __restrict__ bih, const float* __restrict__ bhh, int B)
{
    __shared__ float wst[256 * 33];     // 33792 B
    __shared__ float insm[8 * 128];     // 4096 B  ([hl(64) | rg(64)] per graph)
    __shared__ float gsm[8 * 256];      // 8192 B
    int t = threadIdx.x;
    int b0 = blockIdx.x * 8;

    for (int i = t; i < 8 * 128; i += 256) {
        int g = i >> 7, k = i & 127;
        int b = b0 + g;
        float v = 0.0f;
        if (b < B) v = (k < 64) ? g_S[b * 192 + 128 + k] : g_S[b * 192 + 64 + (k - 64)];
        insm[i] = v;
    }

    float acc[8];
    float bsum = bih[t] + bhh[t];
    #pragma unroll
    for (int g = 0; g < 8; ++g) acc[g] = bsum;

    for (int c = 0; c < 4; ++c) {
        __syncthreads();
        for (int i = t; i < 8192; i += 256) {
            int j = i >> 5, kk = i & 31;
            wst[j * 33 + kk] = g_LW[j * 128 + c * 32 + kk];
        }
        __syncthreads();
        #pragma unroll 8
        for (int kk = 0; kk < 32; ++kk) {
            float w = wst[t * 33 + kk];
            #pragma unroll
            for (int g = 0; g < 8; ++g)
                acc[g] = fmaf(w, insm[g * 128 + c * 32 + kk], acc[g]);
        }
    }

    #pragma unroll
    for (int g = 0; g < 8; ++g) gsm[g * 256 + t] = acc[g];
    __syncthreads();

    for (int i = t; i < 8 * 64; i += 256) {
        int g = i >> 6, hh = i & 63;
        int b = b0 + g;
        if (b >= B) continue;
        float ig = fast_sigm(gsm[g * 256 + hh]);
        float fg = fast_sigm(gsm[g * 256 + 64 + hh]);
        float gg = fast_tanh(gsm[g * 256 + 128 + hh]);
        float og = fast_sigm(gsm[g * 256 + 192 + hh]);
        float cnew = fg * g_cl[b * 64 + hh] + ig * gg;
        g_cl[b * 64 + hh] = cnew;
        g_S[b * 192 + 128 + hh] = og * fast_tanh(cnew);
    }
}

// ---------------- Set2Set attention step (128 threads / graph, R12 form) ----------------
__global__ void __launch_bounds__(128) attn_kernel(int B)
{
    __shared__ float qs[64];
    __shared__ float wm[4], ws[4];
    __shared__ float rgS[64];
    int t = threadIdx.x, b = blockIdx.x;
    if (t < 64) qs[t] = g_S[b * 192 + 128 + t];
    __syncthreads();
    int n0 = g_seg[b], n1 = g_seg[b + 1];
    int w = t >> 5, lid = t & 31;

    float mr = -1e30f, sr = 0.0f;
    for (int n = n0 + w; n < n1; n += 4) {
        const float* orow = g_out + (size_t)n * 64;
        float p = orow[lid] * qs[lid] + orow[32 + lid] * qs[32 + lid];
        #pragma unroll
        for (int off = 16; off; off >>= 1) p += __shfl_xor_sync(0xffffffffu, p, off);
        if (lid == 0) g_cnt[n] = p;
        if (p > mr) { sr *= __expf(mr - p); mr = p; }
        sr += __expf(p - mr);
    }
    if (lid == 0) { wm[w] = mr; ws[w] = sr; }
    __syncthreads();
    float m = fmaxf(fmaxf(wm[0], wm[1]), fmaxf(wm[2], wm[3]));
    float denom = ws[0] * __expf(wm[0] - m) + ws[1] * __expf(wm[1] - m)
                + ws[2] * __expf(wm[2] - m) + ws[3] * __expf(wm[3] - m);

    int col = t & 63, half = t >> 6;
    float rg = 0.0f;
    for (int n = n0 + half; n < n1; n += 2)
        rg = fmaf(__expf(g_cnt[n] - m), g_out[(size_t)n * 64 + col], rg);
    if (half) rgS[col] = rg;
    __syncthreads();
    if (!half) {
        rg += rgS[col];
        if (n1 > n0) rg /= denom;
        g_S[b * 192 + col]      = qs[col];
        g_S[b * 192 + 64 + col] = rg;
    }
}

// ---------------- readout ----------------
__global__ void __launch_bounds__(64) readout_kernel(
    const float* __restrict__ fc1_w, const float* __restrict__ fc1_b,
    const float* __restrict__ fc2_w, const float* __restrict__ fc2_b,
    float* __restrict__ y, int B)
{
    __shared__ float qsm[8 * 128];
    __shared__ float red[2];
    int t = threadIdx.x;
    int b0 = blockIdx.x * 8;
    for (int i = t; i < 1024; i += 64) {
        int g = i >> 7, k = i & 127;
        qsm[i] = (b0 + g < B) ? g_S[(b0 + g) * 192 + k] : 0.0f;
    }
    __syncthreads();
    float w2 = fc2_w[t];
    float b1 = fc1_b[t];
    for (int g = 0; g < 8; ++g) {
        float a = b1;
        #pragma unroll 8
        for (int k = 0; k < 128; ++k) a = fmaf(qsm[g * 128 + k], fc1_w[k * 64 + t], a);
        a = fmaxf(a, 0.0f);
        float p = a * w2;
        #pragma unroll
        for (int off = 16; off; off >>= 1) p += __shfl_xor_sync(0xffffffffu, p, off);
        if ((t & 31) == 0) red[t >> 5] = p;
        __syncthreads();
        if (t == 0 && b0 + g < B) y[b0 + g] = red[0] + red[1] + fc2_b[0];
        __syncthreads();
    }
}

// ---------------- launch ----------------
extern "C" void kernel_launch(void* const* d_in, const int* in_sizes, int n_in,
                              void* d_out, int out_size)
{
    const float* x         = (const float*)d_in[0];
    const float* edge_attr = (const float*)d_in[1];
    const int*   edge_index= (const int*)  d_in[2];
    const int*   batch     = (const int*)  d_in[3];
    const float* w_e1      = (const float*)d_in[4];
    const float* b_e1      = (const float*)d_in[5];
    const float* w_e2      = (const float*)d_in[6];
    const float* b_e2      = (const float*)d_in[7];
    const float* root      = (const float*)d_in[8];
    const float* conv_bias = (const float*)d_in[9];
    const float* gru_wih   = (const float*)d_in[10];
    const float* gru_whh   = (const float*)d_in[11];
    const float* gru_bih   = (const float*)d_in[12];
    const float* gru_bhh   = (const float*)d_in[13];
    const float* lstm_wih  = (const float*)d_in[14];
    const float* lstm_whh  = (const float*)d_in[15];
    const float* lstm_bih  = (const float*)d_in[16];
    const float* lstm_bhh  = (const float*)d_in[17];
    const float* fc1_w     = (const float*)d_in[18];
    const float* fc1_b     = (const float*)d_in[19];
    const float* fc2_w     = (const float*)d_in[20];
    const float* fc2_b     = (const float*)d_in[21];
    float* y = (float*)d_out;

    int N = in_sizes[0] / 16;
    int E = in_sizes[1] / 4;
    int B = out_size;

    static int smem_set = 0;
    if (!smem_set) {
        cudaFuncSetAttribute(edge_kernel3, cudaFuncAttributeMaxDynamicSharedMemorySize, EK3_SMEM);
        cudaFuncSetAttribute(gru_node_kernel, cudaFuncAttributeMaxDynamicSharedMemorySize, GRU_SMEM);
        smem_set = 1;
    }

    // lstm_kernel (1st iter) is the 4th launch (ncu capture window).
    setup_kernel<<<SETUP_BLOCKS, 256>>>(w_e2, gru_wih, gru_whh, gru_bih, gru_bhh,
                                        lstm_wih, lstm_whh, batch, N, B);
    edge_kernel3<<<(E + 127) / 128, 256, EK3_SMEM>>>(x, edge_attr, edge_index, w_e1, b_e1, b_e2, E);
    gru_node_kernel<<<(N + 63) / 64, 256, GRU_SMEM>>>(x, root, conv_bias, N);
    for (int i = 0; i < 3; ++i) {
        lstm_kernel<<<(B + 7) / 8, 256>>>(lstm_bih, lstm_bhh, B);
        attn_kernel<<<B, 128>>>(B);
    }
    readout_kernel<<<(B + 7) / 8, 64>>>(fc1_w, fc1_b, fc2_w, fc2_b, y, B);
}

// round 16
// speedup vs baseline: 1.1774x; 1.0586x over previous
#include <cuda_runtime.h>
#include <cuda_bf16.h>
#include <cuda_fp16.h>
#include <math.h>

typedef unsigned long long ull;
typedef unsigned int uint;

#define MAXN 131072
#define MAXE 262144
#define MAXB 4096

// ---------------- device scratch ----------------
__device__ float g_msum[(size_t)MAXN * 64];
__device__ float g_cnt[MAXN];              // reused as attention e-buffer later
__device__ float g_out[(size_t)MAXN * 64];
__device__ float g_S[MAXB * 192];          // per graph: [0:128]=q_star, [128:192]=hl
__device__ float g_cl[MAXB * 64];
__device__ int   g_seg[MAXB + 1];
// edge GEMM: fp16 w_e2 (single), per-chunk smem images (16 chunks x 16384 B)
__device__ unsigned char g_W2hi[16 * 16384];
// GRU GEMM: Wg fp16 smem image [256 rows x 128 B], epilogue-friendly col order
__device__ unsigned char g_GBhi[32768];
__device__ float g_gbias[256];
// LSTM combined weights: row j (gate 0..255), col k (0..127): k<64 -> wih[:, :64]+whh; k>=64 -> wih[:, 64:]
__device__ float g_LW[256 * 128];

// ---------------- helpers ----------------
__device__ __forceinline__ float fast_sigm(float x) {
    x = fminf(fmaxf(x, -30.0f), 30.0f);
    return __fdividef(1.0f, 1.0f + __expf(-x));
}
__device__ __forceinline__ float fast_tanh(float x) {
    x = fminf(fmaxf(x, -15.0f), 15.0f);
    float t = __expf(2.0f * x);
    return 1.0f - __fdividef(2.0f, 1.0f + t);
}
__device__ __forceinline__ uint smem_u32(const void* p) {
    uint a; asm("{ .reg .u64 t; cvta.to.shared.u64 t, %1; cvt.u32.u64 %0, t; }" : "=r"(a) : "l"(p));
    return a;
}
__device__ __forceinline__ void ldsm4(uint* r, uint addr) {
    asm volatile("ldmatrix.sync.aligned.m8n8.x4.shared.b16 {%0,%1,%2,%3}, [%4];"
        : "=r"(r[0]), "=r"(r[1]), "=r"(r[2]), "=r"(r[3]) : "r"(addr));
}
__device__ __forceinline__ void mma16816(float* d, const uint* a, const uint* b) {
    asm volatile("mma.sync.aligned.m16n8k16.row.col.f32.f16.f16.f32 "
        "{%0,%1,%2,%3}, {%4,%5,%6,%7}, {%8,%9}, {%0,%1,%2,%3};"
        : "+f"(d[0]), "+f"(d[1]), "+f"(d[2]), "+f"(d[3])
        : "r"(a[0]), "r"(a[1]), "r"(a[2]), "r"(a[3]), "r"(b[0]), "r"(b[1]));
}
__device__ __forceinline__ void cp16(uint dst, const void* src) {
    asm volatile("cp.async.ca.shared.global [%0], [%1], 16;" :: "r"(dst), "l"(src));
}
__device__ __forceinline__ void red2(float* p, float a, float b) {
    asm volatile("red.global.add.v2.f32 [%0], {%1, %2};" :: "l"(p), "f"(a), "f"(b) : "memory");
}

// ---------------- merged setup: w2 prep + gru prep + lstm prep + zero + seg ----------------
__device__ __forceinline__ void gru_col_decode(int c, int& j, int& gate) {
    int w = c >> 6, rem = c & 63;
    int half = rem >> 5, within = rem & 31;
    int tile = within >> 3, colin = within & 7;
    j = w * 16 + tile * 4 + (colin >> 1);
    gate = half * 2 + (colin & 1);
}

#define SB_W2   0        // [0, 512)   w_e2 images
#define SB_GRU  512      // [512, 577) gru images + bias
#define SB_LW   577      // [577, 705) lstm combined weights
#define SB_ZERO 705      // [705, 1729) zero scratch (1024 blocks, grid-stride)
#define SB_SEG  1729     // [1729, 1746) segment offsets
#define SETUP_BLOCKS 1746

__global__ void setup_kernel(const float* __restrict__ w_e2,
                             const float* __restrict__ gwih, const float* __restrict__ gwhh,
                             const float* __restrict__ gbih, const float* __restrict__ gbhh,
                             const float* __restrict__ lwih, const float* __restrict__ lwhh,
                             const int* __restrict__ batch, int N, int B)
{
    int bid = blockIdx.x;
    int t = threadIdx.x;
    if (bid < SB_GRU) {
        int idx = bid * 256 + t;
        int m = idx >> 10, j = idx & 1023;     // m = k, j = d*64+h
        __half hi = __float2half_rn(w_e2[idx]);
        int nc = j >> 6, r = j & 63;
        int c = m >> 3;
        int off = r * 256 + ((c ^ (r & 7)) << 4) + (m & 7) * 2;
        *(__half*)(g_W2hi + nc * 16384 + off) = hi;
    } else if (bid < SB_LW) {
        int idx = (bid - SB_GRU) * 256 + t;
        if (idx < 16384) {
            int c = idx >> 6, k = idx & 63;
            int j, gate;
            gru_col_decode(c, j, gate);
            float v;
            if (gate == 0)      v = gwih[j * 64 + k] + gwhh[j * 64 + k];
            else if (gate == 1) v = gwih[(64 + j) * 64 + k] + gwhh[(64 + j) * 64 + k];
            else if (gate == 2) v = gwih[(128 + j) * 64 + k];
            else                v = gwhh[(128 + j) * 64 + k];
            __half hi = __float2half_rn(v);
            int off = c * 128 + (((k >> 3) ^ (c & 7)) << 4) + (k & 7) * 2;
            *(__half*)(g_GBhi + off) = hi;
        } else if (idx < 16640) {
            int c = idx - 16384;
            int j, gate;
            gru_col_decode(c, j, gate);
            float v;
            if (gate == 0)      v = gbih[j] + gbhh[j];
            else if (gate == 1) v = gbih[64 + j] + gbhh[64 + j];
            else if (gate == 2) v = gbih[128 + j];
            else                v = gbhh[128 + j];
            g_gbias[c] = v;
        }
    } else if (bid < SB_ZERO) {
        int idx = (bid - SB_LW) * 256 + t;   // 0 .. 32767
        int j = idx >> 7, k = idx & 127;
        g_LW[idx] = (k < 64) ? (lwih[j * 128 + k] + lwhh[j * 64 + k]) : lwih[j * 128 + k];
    } else if (bid < SB_SEG) {
        int idx = (bid - SB_ZERO) * 256 + t;
        int stride = 1024 * 256;
        float4 z4 = make_float4(0.f, 0.f, 0.f, 0.f);
        int nm4 = N * 16;
        float4* m4 = (float4*)g_msum;
        for (int i = idx; i < nm4; i += stride) m4[i] = z4;
        for (int i = idx; i < N; i += stride) g_cnt[i] = 0.0f;
        int ns = B * 192;
        for (int i = idx; i < ns; i += stride) g_S[i] = 0.0f;
        int nc = B * 64;
        for (int i = idx; i < nc; i += stride) g_cl[i] = 0.0f;
    } else {
        int b = (bid - SB_SEG) * 256 + t;
        if (b > B) return;
        int lo = 0, hi = N;
        while (lo < hi) { int mid = (lo + hi) >> 1; if (batch[mid] < b) lo = mid + 1; else hi = mid; }
        g_seg[b] = lo;
    }
}

// ---------------- edge kernel: HMMA (single-pass fp16) ----------------
#define O_A   0          // 32768 (A hid fp16, 128 rows x 256 B)
#define O_B   32768      // 2 x 16384 double buffer
#define O_XT  65536      // 8192  (xT [16][128] f32)
#define O_B2  73728      // 4096  (b_e2 1024 f32)
#define O_DST 77824      // 512
#define EK3_SMEM 78336

__global__ void __launch_bounds__(256, 2) edge_kernel3(
    const float* __restrict__ x, const float* __restrict__ edge_attr,
    const int* __restrict__ edge_index,
    const float* __restrict__ w_e1, const float* __restrict__ b_e1,
    const float* __restrict__ b_e2, int E)
{
    extern __shared__ char sm[];
    uint smb = smem_u32(sm);
    float* xT  = (float*)(sm + O_XT);
    float* b2S = (float*)(sm + O_B2);
    int*  dstS = (int*)(sm + O_DST);

    int t = threadIdx.x;
    int wid = t >> 5, lane = t & 31;
    int mw = wid & 3, nw = wid >> 2;
    int e0 = blockIdx.x * 128;

    // prefetch B chunk 0 (16 KB)
    {
        uint dst = smb + O_B + t * 16;
        const char* sh = (const char*)g_W2hi + t * 16;
        #pragma unroll
        for (int i = 0; i < 4; ++i) cp16(dst + i * 4096, sh + i * 4096);
        asm volatile("cp.async.commit_group;");
    }

    for (int i = t; i < 1024; i += 256) b2S[i] = b_e2[i];

    if (t < 128) {
        int e = e0 + t;
        int dd = -1;
        if (e < E) {
            int s = edge_index[e];
            dd = edge_index[E + e];
            const float4* xr = reinterpret_cast<const float4*>(x + (size_t)s * 16);
            #pragma unroll
            for (int q = 0; q < 4; ++q) {
                float4 v = xr[q];
                xT[(q * 4 + 0) * 128 + t] = v.x;
                xT[(q * 4 + 1) * 128 + t] = v.y;
                xT[(q * 4 + 2) * 128 + t] = v.z;
                xT[(q * 4 + 3) * 128 + t] = v.w;
            }
            atomicAdd(&g_cnt[dd], 1.0f);
        } else {
            #pragma unroll
            for (int q = 0; q < 16; ++q) xT[q * 128 + t] = 0.0f;
        }
        dstS[t] = dd;
    }

    // form A = fp16(hid)
    {
        int row = t >> 1;
        int cbase = (t & 1) * 8;
        int e = e0 + row;
        float ea0 = 0.f, ea1 = 0.f, ea2 = 0.f, ea3 = 0.f;
        if (e < E) {
            float4 ea = reinterpret_cast<const float4*>(edge_attr)[e];
            ea0 = ea.x; ea1 = ea.y; ea2 = ea.z; ea3 = ea.w;
        }
        #pragma unroll
        for (int c = cbase; c < cbase + 8; ++c) {
            uint h4[4];
            #pragma unroll
            for (int p = 0; p < 4; ++p) {
                int k0 = c * 8 + p * 2;
                float2 w0 = __ldg((const float2*)(w_e1 + k0));
                float2 w1 = __ldg((const float2*)(w_e1 + 128 + k0));
                float2 w2 = __ldg((const float2*)(w_e1 + 256 + k0));
                float2 w3 = __ldg((const float2*)(w_e1 + 384 + k0));
                float2 bb = __ldg((const float2*)(b_e1 + k0));
                float h0 = fmaf(ea3, w3.x, fmaf(ea2, w2.x, fmaf(ea1, w1.x, fmaf(ea0, w0.x, bb.x))));
                float h1 = fmaf(ea3, w3.y, fmaf(ea2, w2.y, fmaf(ea1, w1.y, fmaf(ea0, w0.y, bb.y))));
                __half2 hh = __floats2half2_rn(fmaxf(h0, 0.0f), fmaxf(h1, 0.0f));
                h4[p] = *reinterpret_cast<uint*>(&hh);
            }
            int off = row * 256 + ((c ^ (row & 7)) << 4);
            *(uint4*)(sm + O_A + off) = make_uint4(h4[0], h4[1], h4[2], h4[3]);
        }
    }

    float macc[2][4][4];
    #pragma unroll
    for (int a = 0; a < 2; ++a)
        #pragma unroll
        for (int b = 0; b < 4; ++b)
            #pragma unroll
            for (int r = 0; r < 4; ++r) macc[a][b][r] = 0.0f;

    uint smA = smb + O_A;

    for (int nc = 0; nc < 16; ++nc) {
        asm volatile("cp.async.wait_group 0;" ::: "memory");
        __syncthreads();
        uint smBbuf = smb + O_B + (nc & 1) * 16384;

        if (nc < 15) {
            uint dst = smb + O_B + ((nc + 1) & 1) * 16384 + t * 16;
            const char* sh = (const char*)g_W2hi + (nc + 1) * 16384 + t * 16;
            #pragma unroll
            for (int i = 0; i < 4; ++i) cp16(dst + i * 4096, sh + i * 4096);
            asm volatile("cp.async.commit_group;");
        }

        float dacc[2][4][4];
        #pragma unroll
        for (int a = 0; a < 2; ++a)
            #pragma unroll
            for (int b = 0; b < 4; ++b)
                #pragma unroll
                for (int r = 0; r < 4; ++r) dacc[a][b][r] = 0.0f;

        #pragma unroll
        for (int kt = 0; kt < 8; ++kt) {
            uint a0[4], a1[4];
            {
                int mi = lane >> 3;
                int arow = mw * 32 + (lane & 7) + (mi & 1) * 8;
                int ac = 2 * kt + (mi >> 1);
                uint addr = smA + arow * 256 + ((ac ^ (arow & 7)) << 4);
                ldsm4(a0, addr);
                ldsm4(a1, addr + 16 * 256);
            }
            uint bh[2][4];
            {
                int mi = lane >> 3;
                int nrow = nw * 32 + (mi >> 1) * 8 + (lane & 7);
                int bc = 2 * kt + (mi & 1);
                uint aH = smBbuf + nrow * 256 + ((bc ^ (nrow & 7)) << 4);
                ldsm4(bh[0], aH);
                ldsm4(bh[1], aH + 4096);
            }
            #pragma unroll
            for (int mt = 0; mt < 2; ++mt) {
                const uint* av = mt ? a1 : a0;
                #pragma unroll
                for (int ng = 0; ng < 2; ++ng) {
                    #pragma unroll
                    for (int s = 0; s < 2; ++s)
                        mma16816(dacc[mt][ng * 2 + s], av, &bh[ng][s * 2]);
                }
            }
        }

        // epilogue: msg += x[e,nc] * (D + b_e2)
        {
            int rb = mw * 32 + (lane >> 2);
            float xv00 = xT[nc * 128 + rb];
            float xv01 = xT[nc * 128 + rb + 8];
            float xv10 = xT[nc * 128 + rb + 16];
            float xv11 = xT[nc * 128 + rb + 24];
            #pragma unroll
            for (int mt = 0; mt < 2; ++mt) {
                float xa = mt ? xv10 : xv00;
                float xb = mt ? xv11 : xv01;
                #pragma unroll
                for (int nt = 0; nt < 4; ++nt) {
                    int col = nw * 32 + nt * 8 + 2 * (lane & 3);
                    float b0v = b2S[nc * 64 + col];
                    float b1v = b2S[nc * 64 + col + 1];
                    macc[mt][nt][0] = fmaf(xa, dacc[mt][nt][0] + b0v, macc[mt][nt][0]);
                    macc[mt][nt][1] = fmaf(xa, dacc[mt][nt][1] + b1v, macc[mt][nt][1]);
                    macc[mt][nt][2] = fmaf(xb, dacc[mt][nt][2] + b0v, macc[mt][nt][2]);
                    macc[mt][nt][3] = fmaf(xb, dacc[mt][nt][3] + b1v, macc[mt][nt][3]);
                }
            }
        }
    }

    // scatter: vectorized reductions (red.v2)
    #pragma unroll
    for (int mt = 0; mt < 2; ++mt) {
        #pragma unroll
        for (int half = 0; half < 2; ++half) {
            int row = mw * 32 + mt * 16 + (lane >> 2) + half * 8;
            int dd = dstS[row];
            if (dd < 0) continue;
            float* mr = g_msum + (size_t)dd * 64;
            #pragma unroll
            for (int nt = 0; nt < 4; ++nt) {
                int col = nw * 32 + nt * 8 + 2 * (lane & 3);
                red2(mr + col, macc[mt][nt][half * 2], macc[mt][nt][half * 2 + 1]);
            }
        }
    }
}

// ---------------- fused node + GRU x3 via HMMA (single-pass fp16, 2m x 4n grid) ----------------
#define G_HS   0        // 64 x 65 f32 = 16640 (col 64 = inv_cnt)
#define G_AHI  16640    // 8192 (overlay: root 4096 + xS 4096 during node phase)
#define G_BHI  24832    // 32768
#define G_BIAS 57600    // 1024
#define GRU_SMEM 58624

__global__ void __launch_bounds__(256, 2) gru_node_kernel(
    const float* __restrict__ x, const float* __restrict__ root,
    const float* __restrict__ conv_bias, int N)
{
    extern __shared__ char sm2[];
    uint smb = smem_u32(sm2);
    float* hS    = (float*)(sm2 + G_HS);
    float* biasS = (float*)(sm2 + G_BIAS);
    float* rootS = (float*)(sm2 + G_AHI);          // node-phase overlay
    float* xS    = (float*)(sm2 + G_AHI + 4096);

    int t = threadIdx.x, wid = t >> 5, lane = t & 31;
    int n0 = blockIdx.x * 64;

    // stage B (32 KB) asynchronously — overlaps node phase
    {
        uint dh = smb + G_BHI + t * 16;
        const char* sh = (const char*)g_GBhi + t * 16;
        #pragma unroll
        for (int i = 0; i < 8; ++i) cp16(dh + i * 4096, sh + i * 4096);
        asm volatile("cp.async.commit_group;");
    }
    biasS[t] = g_gbias[t];

    // node-phase staging
    for (int i = t; i < 1024; i += 256) rootS[i] = root[i];
    for (int i = t; i < 1024; i += 256) {
        int r = i >> 4, d = i & 15;
        int n = n0 + r;
        xS[i] = (n < N) ? x[(size_t)n * 16 + d] : 0.0f;
    }
    if (t < 64) {
        int n = n0 + t;
        hS[t * 65 + 64] = (n < N) ? __fdividef(1.0f, fmaxf(g_cnt[n], 1.0f)) : 1.0f;
    }
    __syncthreads();

    // node update: hS = relu(msum*inv_cnt + x@root + conv_bias)
    {
        float cbv = __ldg(conv_bias + (t & 63));
        #pragma unroll
        for (int j = 0; j < 16; ++j) {
            int idx = j * 256 + t;
            int r = idx >> 6, c = idx & 63;
            int n = n0 + r;
            float v = 0.0f;
            if (n < N) {
                float acc = cbv;
                const float* xr = xS + r * 16;
                #pragma unroll
                for (int d = 0; d < 16; ++d) acc = fmaf(xr[d], rootS[d * 64 + c], acc);
                v = fmaxf(fmaf(g_msum[(size_t)n * 64 + c], hS[r * 65 + 64], acc), 0.0f);
            }
            hS[r * 65 + c] = v;
        }
    }
    asm volatile("cp.async.wait_group 0;" ::: "memory");
    __syncthreads();

    int mw = wid & 1, nh = wid >> 1;
    int mi = lane >> 3;
    uint smAhi = smb + G_AHI;
    uint smBh = smb + G_BHI;

    for (int step = 0; step < 3; ++step) {
        // convert hS -> fp16 A
        {
            int r = t >> 2, q = t & 3;
            const float* hr = hS + r * 65 + q * 16;
            #pragma unroll
            for (int c2 = 0; c2 < 2; ++c2) {
                uint hi4[4];
                #pragma unroll
                for (int p = 0; p < 4; ++p) {
                    __half2 hh = __floats2half2_rn(hr[c2 * 8 + p * 2], hr[c2 * 8 + p * 2 + 1]);
                    hi4[p] = *reinterpret_cast<uint*>(&hh);
                }
                int cc = q * 2 + c2;
                int off = r * 128 + ((cc ^ (r & 7)) << 4);
                *(uint4*)(sm2 + G_AHI + off) = make_uint4(hi4[0], hi4[1], hi4[2], hi4[3]);
            }
        }
        __syncthreads();

        float acc[16][4];
        #pragma unroll
        for (int i = 0; i < 16; ++i)
            #pragma unroll
            for (int j = 0; j < 4; ++j) acc[i][j] = 0.0f;

        #pragma unroll
        for (int kt = 0; kt < 4; ++kt) {
            uint a0[4], a1[4];
            {
                int arow = mw * 32 + (lane & 7) + (mi & 1) * 8;
                int ac = 2 * kt + (mi >> 1);
                uint aoff = (uint)(arow * 128 + ((ac ^ (arow & 7)) << 4));
                ldsm4(a0, smAhi + aoff);
                ldsm4(a1, smAhi + aoff + 16 * 128);
            }
            #pragma unroll
            for (int g2 = 0; g2 < 4; ++g2) {
                uint bh[4];
                int nrow = nh * 64 + g2 * 16 + (mi >> 1) * 8 + (lane & 7);
                int bc = 2 * kt + (mi & 1);
                uint boff = (uint)(nrow * 128 + ((bc ^ (nrow & 7)) << 4));
                ldsm4(bh, smBh + boff);
                mma16816(acc[0 * 8 + g2 * 2],     a0, bh);
                mma16816(acc[0 * 8 + g2 * 2 + 1], a0, bh + 2);
                mma16816(acc[1 * 8 + g2 * 2],     a1, bh);
                mma16816(acc[1 * 8 + g2 * 2 + 1], a1, bh + 2);
            }
        }
        __syncthreads();   // A reads complete before h' overwrite

        // gates -> h' (no shuffles: rz tiles 0..3 pair with inhn tiles 4..7, same lane/j)
        {
            int qj = lane & 3;
            int rb = lane >> 2;
            #pragma unroll
            for (int mt = 0; mt < 2; ++mt) {
                #pragma unroll
                for (int tp = 0; tp < 4; ++tp) {
                    float* aRZ = acc[mt * 8 + tp];
                    float* aNH = acc[mt * 8 + tp + 4];
                    int cb = nh * 64 + tp * 8 + 2 * qj;
                    float br = biasS[cb],      bz = biasS[cb + 1];
                    float bi = biasS[cb + 32], bn = biasS[cb + 33];
                    int j = nh * 16 + tp * 4 + qj;
                    int ra = mw * 32 + mt * 16 + rb;
                    {
                        float r = fast_sigm(aRZ[0] + br), z = fast_sigm(aRZ[1] + bz);
                        float nv = fast_tanh((aNH[0] + bi) + r * (aNH[1] + bn));
                        float hold = hS[ra * 65 + j];
                        hS[ra * 65 + j] = (1.0f - z) * nv + z * hold;
                    }
                    {
                        float r = fast_sigm(aRZ[2] + br), z = fast_sigm(aRZ[3] + bz);
                        float nv = fast_tanh((aNH[2] + bi) + r * (aNH[3] + bn));
                        float hold = hS[(ra + 8) * 65 + j];
                        hS[(ra + 8) * 65 + j] = (1.0f - z) * nv + z * hold;
                    }
                }
            }
        }
        __syncthreads();
    }

    // coalesced writeback
    #pragma unroll
    for (int j = 0; j < 16; ++j) {
        int idx = j * 256 + t;
        int r = idx >> 6, c = idx & 63;
        int n = n0 + r;
        if (n < N) g_out[(size_t)n * 64 + c] = hS[r * 65 + c];
    }
}

// ---------------- Set2Set LSTM step: 32 graphs/block, weights staged once ----------------
// wst rows padded to 132 floats (33 float4): LDS.128 conflict-free, aligned.
#define L_WST 0          // 256 x 33 float4 = 135168 B
#define L_IN  135168     // 32 x 32 float4 = 16384 B
#define L_GS  151552     // 32 x 256 f32 = 32768 B
#define LSTM_SMEM 184320

__global__ void __launch_bounds__(256, 1) lstm_kernel(
    const float* __restrict__ bih, const float* __restrict__ bhh, int B)
{
    extern __shared__ char lsm[];
    float4* wst4 = (float4*)(lsm + L_WST);
    float4* in4  = (float4*)(lsm + L_IN);
    float*  gsm  = (float*)(lsm + L_GS);
    int t = threadIdx.x;
    int b0 = blockIdx.x * 32;

    // stage weights once: 32768 floats = 8192 float4
    for (int i = t; i < 8192; i += 256) {
        int j = i >> 5, q = i & 31;
        wst4[j * 33 + q] = ((const float4*)g_LW)[i];
    }
    // stage inputs: [32 graphs][128] = [hl(64) | rg(64)]
    for (int i = t; i < 1024; i += 256) {
        int g = i >> 5, q = i & 31;
        int b = b0 + g;
        float4 v = make_float4(0.f, 0.f, 0.f, 0.f);
        if (b < B) {
            if (q < 16) v = *(const float4*)(g_S + b * 192 + 128 + q * 4);
            else        v = *(const float4*)(g_S + b * 192 + 64 + (q - 16) * 4);
        }
        in4[g * 32 + q] = v;
    }
    __syncthreads();

    float acc[32];
    float bsum = bih[t] + bhh[t];
    #pragma unroll
    for (int g = 0; g < 32; ++g) acc[g] = bsum;

    for (int q = 0; q < 32; ++q) {
        float4 w = wst4[t * 33 + q];
        #pragma unroll
        for (int g = 0; g < 32; ++g) {
            float4 v = in4[g * 32 + q];
            acc[g] = fmaf(w.x, v.x, fmaf(w.y, v.y, fmaf(w.z, v.z, fmaf(w.w, v.w, acc[g]))));
        }
    }

    #pragma unroll
    for (int g = 0; g < 32; ++g) gsm[g * 256 + t] = acc[g];
    __syncthreads();

    for (int i = t; i < 32 * 64; i += 256) {
        int g = i >> 6, hh = i & 63;
        int b = b0 + g;
        if (b >= B) continue;
        float ig = fast_sigm(gsm[g * 256 + hh]);
        float fg = fast_sigm(gsm[g * 256 + 64 + hh]);
        float gg = fast_tanh(gsm[g * 256 + 128 + hh]);
        float og = fast_sigm(gsm[g * 256 + 192 + hh]);
        float cnew = fg * g_cl[b * 64 + hh] + ig * gg;
        g_cl[b * 64 + hh] = cnew;
        g_S[b * 192 + 128 + hh] = og * fast_tanh(cnew);
    }
}

// ---------------- Set2Set attention step (128 threads / graph) ----------------
__global__ void __launch_bounds__(128) attn_kernel(int B, int write_q)
{
    __shared__ float qs[64];
    __shared__ float wm[4], ws[4];
    __shared__ float rgS[64];
    int t = threadIdx.x, b = blockIdx.x;
    if (t < 64) qs[t] = g_S[b * 192 + 128 + t];
    __syncthreads();
    int n0 = g_seg[b], n1 = g_seg[b + 1];
    int w = t >> 5, lid = t & 31;

    float mr = -1e30f, sr = 0.0f;
    for (int n = n0 + w; n < n1; n += 4) {
        const float* orow = g_out + (size_t)n * 64;
        float p = orow[lid] * qs[lid] + orow[32 + lid] * qs[32 + lid];
        #pragma unroll
        for (int off = 16; off; off >>= 1) p += __shfl_xor_sync(0xffffffffu, p, off);
        if (lid == 0) g_cnt[n] = p;
        if (p > mr) { sr *= __expf(mr - p); mr = p; }
        sr += __expf(p - mr);
    }
    if (lid == 0) { wm[w] = mr; ws[w] = sr; }
    __syncthreads();
    float m = fmaxf(fmaxf(wm[0], wm[1]), fmaxf(wm[2], wm[3]));
    float denom = ws[0] * __expf(wm[0] - m) + ws[1] * __expf(wm[1] - m)
                + ws[2] * __expf(wm[2] - m) + ws[3] * __expf(wm[3] - m);

    int col = t & 63, half = t >> 6;
    float rg = 0.0f;
    for (int n = n0 + half; n < n1; n += 2)
        rg = fmaf(__expf(g_cnt[n] - m), g_out[(size_t)n * 64 + col], rg);
    if (half) rgS[col] = rg;
    __syncthreads();
    if (!half) {
        rg += rgS[col];
        if (n1 > n0) rg /= denom;
        if (write_q) g_S[b * 192 + col] = qs[col];
        g_S[b * 192 + 64 + col] = rg;
    }
}

// ---------------- readout ----------------
__global__ void __launch_bounds__(64) readout_kernel(
    const float* __restrict__ fc1_w, const float* __restrict__ fc1_b,
    const float* __restrict__ fc2_w, const float* __restrict__ fc2_b,
    float* __restrict__ y, int B)
{
    __shared__ float qsm[8 * 128];
    __shared__ float red[2];
    int t = threadIdx.x;
    int b0 = blockIdx.x * 8;
    for (int i = t; i < 1024; i += 64) {
        int g = i >> 7, k = i & 127;
        qsm[i] = (b0 + g < B) ? g_S[(b0 + g) * 192 + k] : 0.0f;
    }
    __syncthreads();
    float w2 = fc2_w[t];
    float b1 = fc1_b[t];
    for (int g = 0; g < 8; ++g) {
        float a = b1;
        #pragma unroll 8
        for (int k = 0; k < 128; ++k) a = fmaf(qsm[g * 128 + k], fc1_w[k * 64 + t], a);
        a = fmaxf(a, 0.0f);
        float p = a * w2;
        #pragma unroll
        for (int off = 16; off; off >>= 1) p += __shfl_xor_sync(0xffffffffu, p, off);
        if ((t & 31) == 0) red[t >> 5] = p;
        __syncthreads();
        if (t == 0 && b0 + g < B) y[b0 + g] = red[0] + red[1] + fc2_b[0];
        __syncthreads();
    }
}

// ---------------- launch ----------------
extern "C" void kernel_launch(void* const* d_in, const int* in_sizes, int n_in,
                              void* d_out, int out_size)
{
    const float* x         = (const float*)d_in[0];
    const float* edge_attr = (const float*)d_in[1];
    const int*   edge_index= (const int*)  d_in[2];
    const int*   batch     = (const int*)  d_in[3];
    const float* w_e1      = (const float*)d_in[4];
    const float* b_e1      = (const float*)d_in[5];
    const float* w_e2      = (const float*)d_in[6];
    const float* b_e2      = (const float*)d_in[7];
    const float* root      = (const float*)d_in[8];
    const float* conv_bias = (const float*)d_in[9];
    const float* gru_wih   = (const float*)d_in[10];
    const float* gru_whh   = (const float*)d_in[11];
    const float* gru_bih   = (const float*)d_in[12];
    const float* gru_bhh   = (const float*)d_in[13];
    const float* lstm_wih  = (const float*)d_in[14];
    const float* lstm_whh  = (const float*)d_in[15];
    const float* lstm_bih  = (const float*)d_in[16];
    const float* lstm_bhh  = (const float*)d_in[17];
    const float* fc1_w     = (const float*)d_in[18];
    const float* fc1_b     = (const float*)d_in[19];
    const float* fc2_w     = (const float*)d_in[20];
    const float* fc2_b     = (const float*)d_in[21];
    float* y = (float*)d_out;

    int N = in_sizes[0] / 16;
    int E = in_sizes[1] / 4;
    int B = out_size;

    static int smem_set = 0;
    if (!smem_set) {
        cudaFuncSetAttribute(edge_kernel3, cudaFuncAttributeMaxDynamicSharedMemorySize, EK3_SMEM);
        cudaFuncSetAttribute(gru_node_kernel, cudaFuncAttributeMaxDynamicSharedMemorySize, GRU_SMEM);
        cudaFuncSetAttribute(lstm_kernel, cudaFuncAttributeMaxDynamicSharedMemorySize, LSTM_SMEM);
        smem_set = 1;
    }

    // lstm_kernel (1st iter) is the 4th launch (ncu capture window).
    setup_kernel<<<SETUP_BLOCKS, 256>>>(w_e2, gru_wih, gru_whh, gru_bih, gru_bhh,
                                        lstm_wih, lstm_whh, batch, N, B);
    edge_kernel3<<<(E + 127) / 128, 256, EK3_SMEM>>>(x, edge_attr, edge_index, w_e1, b_e1, b_e2, E);
    gru_node_kernel<<<(N + 63) / 64, 256, GRU_SMEM>>>(x, root, conv_bias, N);
    for (int i = 0; i < 3; ++i) {
        lstm_kernel<<<(B + 31) / 32, 256, LSTM_SMEM>>>(lstm_bih, lstm_bhh, B);
        attn_kernel<<<B, 128>>>(B, i == 2);
    }
    readout_kernel<<<(B + 7) / 8, 64>>>(fc1_w, fc1_b, fc2_w, fc2_b, y, B);
}

// round 17
// speedup vs baseline: 1.1925x; 1.0129x over previous
#include <cuda_runtime.h>
#include <cuda_bf16.h>
#include <cuda_fp16.h>
#include <math.h>

typedef unsigned long long ull;
typedef unsigned int uint;

#define MAXN 131072
#define MAXE 262144
#define MAXB 4096

// ---------------- device scratch ----------------
__device__ float g_msum[(size_t)MAXN * 64];
__device__ float g_cnt[MAXN];              // reused as attention e-buffer later
__device__ float g_out[(size_t)MAXN * 64];
__device__ float g_S[MAXB * 192];          // per graph: [0:128]=q_star, [128:192]=hl
__device__ float g_cl[MAXB * 64];
__device__ int   g_seg[MAXB + 1];
// edge GEMM: fp16 w_e2 (single), per-chunk smem images (16 chunks x 16384 B)
__device__ unsigned char g_W2hi[16 * 16384];
// GRU GEMM: Wg fp16 smem image [256 rows x 128 B], epilogue-friendly col order
__device__ unsigned char g_GBhi[32768];
__device__ float g_gbias[256];
// LSTM combined weights: row j (gate 0..255), col k (0..127): k<64 -> wih[:, :64]+whh; k>=64 -> wih[:, 64:]
__device__ float g_LW[256 * 128];

// ---------------- helpers ----------------
__device__ __forceinline__ float fast_sigm(float x) {
    x = fminf(fmaxf(x, -30.0f), 30.0f);
    return __fdividef(1.0f, 1.0f + __expf(-x));
}
__device__ __forceinline__ float fast_tanh(float x) {
    x = fminf(fmaxf(x, -15.0f), 15.0f);
    float t = __expf(2.0f * x);
    return 1.0f - __fdividef(2.0f, 1.0f + t);
}
__device__ __forceinline__ uint smem_u32(const void* p) {
    uint a; asm("{ .reg .u64 t; cvta.to.shared.u64 t, %1; cvt.u32.u64 %0, t; }" : "=r"(a) : "l"(p));
    return a;
}
__device__ __forceinline__ void ldsm4(uint* r, uint addr) {
    asm volatile("ldmatrix.sync.aligned.m8n8.x4.shared.b16 {%0,%1,%2,%3}, [%4];"
        : "=r"(r[0]), "=r"(r[1]), "=r"(r[2]), "=r"(r[3]) : "r"(addr));
}
__device__ __forceinline__ void mma16816(float* d, const uint* a, const uint* b) {
    asm volatile("mma.sync.aligned.m16n8k16.row.col.f32.f16.f16.f32 "
        "{%0,%1,%2,%3}, {%4,%5,%6,%7}, {%8,%9}, {%0,%1,%2,%3};"
        : "+f"(d[0]), "+f"(d[1]), "+f"(d[2]), "+f"(d[3])
        : "r"(a[0]), "r"(a[1]), "r"(a[2]), "r"(a[3]), "r"(b[0]), "r"(b[1]));
}
__device__ __forceinline__ void cp16(uint dst, const void* src) {
    asm volatile("cp.async.ca.shared.global [%0], [%1], 16;" :: "r"(dst), "l"(src));
}
__device__ __forceinline__ void red2(float* p, float a, float b) {
    asm volatile("red.global.add.v2.f32 [%0], {%1, %2};" :: "l"(p), "f"(a), "f"(b) : "memory");
}
__device__ __forceinline__ void sts16(uint addr, __half v) {
    unsigned short u = *reinterpret_cast<unsigned short*>(&v);
    asm volatile("st.shared.b16 [%0], %1;" :: "r"(addr), "h"(u) : "memory");
}
// fp16 A-tile byte offset for element (row r, col k): 128 B rows, XOR-16B swizzle
__device__ __forceinline__ int a16_off(int r, int k) {
    return r * 128 + ((((k >> 3) ^ (r & 7))) << 4) + (k & 7) * 2;
}

// ---------------- merged setup ----------------
__device__ __forceinline__ void gru_col_decode(int c, int& j, int& gate) {
    int w = c >> 6, rem = c & 63;
    int half = rem >> 5, within = rem & 31;
    int tile = within >> 3, colin = within & 7;
    j = w * 16 + tile * 4 + (colin >> 1);
    gate = half * 2 + (colin & 1);
}

#define SB_W2   0
#define SB_GRU  512
#define SB_LW   577
#define SB_ZERO 705
#define SB_SEG  1729
#define SETUP_BLOCKS 1746

__global__ void setup_kernel(const float* __restrict__ w_e2,
                             const float* __restrict__ gwih, const float* __restrict__ gwhh,
                             const float* __restrict__ gbih, const float* __restrict__ gbhh,
                             const float* __restrict__ lwih, const float* __restrict__ lwhh,
                             const int* __restrict__ batch, int N, int B)
{
    int bid = blockIdx.x;
    int t = threadIdx.x;
    if (bid < SB_GRU) {
        int idx = bid * 256 + t;
        int m = idx >> 10, j = idx & 1023;     // m = k, j = d*64+h
        __half hi = __float2half_rn(w_e2[idx]);
        int nc = j >> 6, r = j & 63;
        int c = m >> 3;
        int off = r * 256 + ((c ^ (r & 7)) << 4) + (m & 7) * 2;
        *(__half*)(g_W2hi + nc * 16384 + off) = hi;
    } else if (bid < SB_LW) {
        int idx = (bid - SB_GRU) * 256 + t;
        if (idx < 16384) {
            int c = idx >> 6, k = idx & 63;
            int j, gate;
            gru_col_decode(c, j, gate);
            float v;
            if (gate == 0)      v = gwih[j * 64 + k] + gwhh[j * 64 + k];
            else if (gate == 1) v = gwih[(64 + j) * 64 + k] + gwhh[(64 + j) * 64 + k];
            else if (gate == 2) v = gwih[(128 + j) * 64 + k];
            else                v = gwhh[(128 + j) * 64 + k];
            __half hi = __float2half_rn(v);
            int off = c * 128 + (((k >> 3) ^ (c & 7)) << 4) + (k & 7) * 2;
            *(__half*)(g_GBhi + off) = hi;
        } else if (idx < 16640) {
            int c = idx - 16384;
            int j, gate;
            gru_col_decode(c, j, gate);
            float v;
            if (gate == 0)      v = gbih[j] + gbhh[j];
            else if (gate == 1) v = gbih[64 + j] + gbhh[64 + j];
            else if (gate == 2) v = gbih[128 + j];
            else                v = gbhh[128 + j];
            g_gbias[c] = v;
        }
    } else if (bid < SB_ZERO) {
        int idx = (bid - SB_LW) * 256 + t;   // 0 .. 32767
        int j = idx >> 7, k = idx & 127;
        g_LW[idx] = (k < 64) ? (lwih[j * 128 + k] + lwhh[j * 64 + k]) : lwih[j * 128 + k];
    } else if (bid < SB_SEG) {
        int idx = (bid - SB_ZERO) * 256 + t;
        int stride = 1024 * 256;
        float4 z4 = make_float4(0.f, 0.f, 0.f, 0.f);
        int nm4 = N * 16;
        float4* m4 = (float4*)g_msum;
        for (int i = idx; i < nm4; i += stride) m4[i] = z4;
        for (int i = idx; i < N; i += stride) g_cnt[i] = 0.0f;
        int ns = B * 192;
        for (int i = idx; i < ns; i += stride) g_S[i] = 0.0f;
        int nc = B * 64;
        for (int i = idx; i < nc; i += stride) g_cl[i] = 0.0f;
    } else {
        int b = (bid - SB_SEG) * 256 + t;
        if (b > B) return;
        int lo = 0, hi = N;
        while (lo < hi) { int mid = (lo + hi) >> 1; if (batch[mid] < b) lo = mid + 1; else hi = mid; }
        g_seg[b] = lo;
    }
}

// ---------------- edge kernel: HMMA (single-pass fp16) ----------------
#define O_A   0          // 32768 (A hid fp16, 128 rows x 256 B)
#define O_B   32768      // 2 x 16384 double buffer
#define O_XT  65536      // 8192  (xT [16][128] f32)
#define O_B2  73728      // 4096  (b_e2 1024 f32)
#define O_DST 77824      // 512
#define EK3_SMEM 78336

__global__ void __launch_bounds__(256, 2) edge_kernel3(
    const float* __restrict__ x, const float* __restrict__ edge_attr,
    const int* __restrict__ edge_index,
    const float* __restrict__ w_e1, const float* __restrict__ b_e1,
    const float* __restrict__ b_e2, int E)
{
    extern __shared__ char sm[];
    uint smb = smem_u32(sm);
    float* xT  = (float*)(sm + O_XT);
    float* b2S = (float*)(sm + O_B2);
    int*  dstS = (int*)(sm + O_DST);

    int t = threadIdx.x;
    int wid = t >> 5, lane = t & 31;
    int mw = wid & 3, nw = wid >> 2;
    int e0 = blockIdx.x * 128;

    // prefetch B chunk 0 (16 KB)
    {
        uint dst = smb + O_B + t * 16;
        const char* sh = (const char*)g_W2hi + t * 16;
        #pragma unroll
        for (int i = 0; i < 4; ++i) cp16(dst + i * 4096, sh + i * 4096);
        asm volatile("cp.async.commit_group;");
    }

    for (int i = t; i < 1024; i += 256) b2S[i] = b_e2[i];

    if (t < 128) {
        int e = e0 + t;
        int dd = -1;
        if (e < E) {
            int s = edge_index[e];
            dd = edge_index[E + e];
            const float4* xr = reinterpret_cast<const float4*>(x + (size_t)s * 16);
            #pragma unroll
            for (int q = 0; q < 4; ++q) {
                float4 v = xr[q];
                xT[(q * 4 + 0) * 128 + t] = v.x;
                xT[(q * 4 + 1) * 128 + t] = v.y;
                xT[(q * 4 + 2) * 128 + t] = v.z;
                xT[(q * 4 + 3) * 128 + t] = v.w;
            }
            atomicAdd(&g_cnt[dd], 1.0f);
        } else {
            #pragma unroll
            for (int q = 0; q < 16; ++q) xT[q * 128 + t] = 0.0f;
        }
        dstS[t] = dd;
    }

    // form A = fp16(hid)
    {
        int row = t >> 1;
        int cbase = (t & 1) * 8;
        int e = e0 + row;
        float ea0 = 0.f, ea1 = 0.f, ea2 = 0.f, ea3 = 0.f;
        if (e < E) {
            float4 ea = reinterpret_cast<const float4*>(edge_attr)[e];
            ea0 = ea.x; ea1 = ea.y; ea2 = ea.z; ea3 = ea.w;
        }
        #pragma unroll
        for (int c = cbase; c < cbase + 8; ++c) {
            uint h4[4];
            #pragma unroll
            for (int p = 0; p < 4; ++p) {
                int k0 = c * 8 + p * 2;
                float2 w0 = __ldg((const float2*)(w_e1 + k0));
                float2 w1 = __ldg((const float2*)(w_e1 + 128 + k0));
                float2 w2 = __ldg((const float2*)(w_e1 + 256 + k0));
                float2 w3 = __ldg((const float2*)(w_e1 + 384 + k0));
                float2 bb = __ldg((const float2*)(b_e1 + k0));
                float h0 = fmaf(ea3, w3.x, fmaf(ea2, w2.x, fmaf(ea1, w1.x, fmaf(ea0, w0.x, bb.x))));
                float h1 = fmaf(ea3, w3.y, fmaf(ea2, w2.y, fmaf(ea1, w1.y, fmaf(ea0, w0.y, bb.y))));
                __half2 hh = __floats2half2_rn(fmaxf(h0, 0.0f), fmaxf(h1, 0.0f));
                h4[p] = *reinterpret_cast<uint*>(&hh);
            }
            int off = row * 256 + ((c ^ (row & 7)) << 4);
            *(uint4*)(sm + O_A + off) = make_uint4(h4[0], h4[1], h4[2], h4[3]);
        }
    }

    float macc[2][4][4];
    #pragma unroll
    for (int a = 0; a < 2; ++a)
        #pragma unroll
        for (int b = 0; b < 4; ++b)
            #pragma unroll
            for (int r = 0; r < 4; ++r) macc[a][b][r] = 0.0f;

    uint smA = smb + O_A;

    for (int nc = 0; nc < 16; ++nc) {
        asm volatile("cp.async.wait_group 0;" ::: "memory");
        __syncthreads();
        uint smBbuf = smb + O_B + (nc & 1) * 16384;

        if (nc < 15) {
            uint dst = smb + O_B + ((nc + 1) & 1) * 16384 + t * 16;
            const char* sh = (const char*)g_W2hi + (nc + 1) * 16384 + t * 16;
            #pragma unroll
            for (int i = 0; i < 4; ++i) cp16(dst + i * 4096, sh + i * 4096);
            asm volatile("cp.async.commit_group;");
        }

        float dacc[2][4][4];
        #pragma unroll
        for (int a = 0; a < 2; ++a)
            #pragma unroll
            for (int b = 0; b < 4; ++b)
                #pragma unroll
                for (int r = 0; r < 4; ++r) dacc[a][b][r] = 0.0f;

        #pragma unroll
        for (int kt = 0; kt < 8; ++kt) {
            uint a0[4], a1[4];
            {
                int mi = lane >> 3;
                int arow = mw * 32 + (lane & 7) + (mi & 1) * 8;
                int ac = 2 * kt + (mi >> 1);
                uint addr = smA + arow * 256 + ((ac ^ (arow & 7)) << 4);
                ldsm4(a0, addr);
                ldsm4(a1, addr + 16 * 256);
            }
            uint bh[2][4];
            {
                int mi = lane >> 3;
                int nrow = nw * 32 + (mi >> 1) * 8 + (lane & 7);
                int bc = 2 * kt + (mi & 1);
                uint aH = smBbuf + nrow * 256 + ((bc ^ (nrow & 7)) << 4);
                ldsm4(bh[0], aH);
                ldsm4(bh[1], aH + 4096);
            }
            #pragma unroll
            for (int mt = 0; mt < 2; ++mt) {
                const uint* av = mt ? a1 : a0;
                #pragma unroll
                for (int ng = 0; ng < 2; ++ng) {
                    #pragma unroll
                    for (int s = 0; s < 2; ++s)
                        mma16816(dacc[mt][ng * 2 + s], av, &bh[ng][s * 2]);
                }
            }
        }

        // epilogue: msg += x[e,nc] * (D + b_e2)
        {
            int rb = mw * 32 + (lane >> 2);
            float xv00 = xT[nc * 128 + rb];
            float xv01 = xT[nc * 128 + rb + 8];
            float xv10 = xT[nc * 128 + rb + 16];
            float xv11 = xT[nc * 128 + rb + 24];
            #pragma unroll
            for (int mt = 0; mt < 2; ++mt) {
                float xa = mt ? xv10 : xv00;
                float xb = mt ? xv11 : xv01;
                #pragma unroll
                for (int nt = 0; nt < 4; ++nt) {
                    int col = nw * 32 + nt * 8 + 2 * (lane & 3);
                    float b0v = b2S[nc * 64 + col];
                    float b1v = b2S[nc * 64 + col + 1];
                    macc[mt][nt][0] = fmaf(xa, dacc[mt][nt][0] + b0v, macc[mt][nt][0]);
                    macc[mt][nt][1] = fmaf(xa, dacc[mt][nt][1] + b1v, macc[mt][nt][1]);
                    macc[mt][nt][2] = fmaf(xb, dacc[mt][nt][2] + b0v, macc[mt][nt][2]);
                    macc[mt][nt][3] = fmaf(xb, dacc[mt][nt][3] + b1v, macc[mt][nt][3]);
                }
            }
        }
    }

    // scatter: vectorized reductions (red.v2)
    #pragma unroll
    for (int mt = 0; mt < 2; ++mt) {
        #pragma unroll
        for (int half = 0; half < 2; ++half) {
            int row = mw * 32 + mt * 16 + (lane >> 2) + half * 8;
            int dd = dstS[row];
            if (dd < 0) continue;
            float* mr = g_msum + (size_t)dd * 64;
            #pragma unroll
            for (int nt = 0; nt < 4; ++nt) {
                int col = nw * 32 + nt * 8 + 2 * (lane & 3);
                red2(mr + col, macc[mt][nt][half * 2], macc[mt][nt][half * 2 + 1]);
            }
        }
    }
}

// ---------------- fused node + GRU x3 via HMMA; A written in-place by producers ----------------
#define G_HS   0        // 64 x 65 f32 = 16640 (col 64 = inv_cnt)
#define G_AHI  16640    // 8192 A fp16 tile
#define G_BHI  24832    // 32768
#define G_BIAS 57600    // 1024
#define G_ROOT 58624    // 4096
#define G_X    62720    // 4096
#define GRU_SMEM 66816

__global__ void __launch_bounds__(256, 2) gru_node_kernel(
    const float* __restrict__ x, const float* __restrict__ root,
    const float* __restrict__ conv_bias, int N)
{
    extern __shared__ char sm2[];
    uint smb = smem_u32(sm2);
    float* hS    = (float*)(sm2 + G_HS);
    float* biasS = (float*)(sm2 + G_BIAS);
    float* rootS = (float*)(sm2 + G_ROOT);
    float* xS    = (float*)(sm2 + G_X);

    int t = threadIdx.x, wid = t >> 5, lane = t & 31;
    int n0 = blockIdx.x * 64;

    // stage B (32 KB) asynchronously — overlaps node phase
    {
        uint dh = smb + G_BHI + t * 16;
        const char* sh = (const char*)g_GBhi + t * 16;
        #pragma unroll
        for (int i = 0; i < 8; ++i) cp16(dh + i * 4096, sh + i * 4096);
        asm volatile("cp.async.commit_group;");
    }
    biasS[t] = g_gbias[t];

    // node-phase staging
    for (int i = t; i < 1024; i += 256) rootS[i] = root[i];
    for (int i = t; i < 1024; i += 256) {
        int r = i >> 4, d = i & 15;
        int n = n0 + r;
        xS[i] = (n < N) ? x[(size_t)n * 16 + d] : 0.0f;
    }
    if (t < 64) {
        int n = n0 + t;
        hS[t * 65 + 64] = (n < N) ? __fdividef(1.0f, fmaxf(g_cnt[n], 1.0f)) : 1.0f;
    }
    __syncthreads();

    // node update: hS = relu(msum*inv_cnt + x@root + conv_bias); write fp16 A directly
    {
        float cbv = __ldg(conv_bias + (t & 63));
        #pragma unroll
        for (int j = 0; j < 16; ++j) {
            int idx = j * 256 + t;
            int r = idx >> 6, c = idx & 63;
            int n = n0 + r;
            float v = 0.0f;
            if (n < N) {
                float acc = cbv;
                const float* xr = xS + r * 16;
                #pragma unroll
                for (int d = 0; d < 16; ++d) acc = fmaf(xr[d], rootS[d * 64 + c], acc);
                v = fmaxf(fmaf(g_msum[(size_t)n * 64 + c], hS[r * 65 + 64], acc), 0.0f);
            }
            hS[r * 65 + c] = v;
            sts16(smb + G_AHI + a16_off(r, c), __float2half_rn(v));
        }
    }
    asm volatile("cp.async.wait_group 0;" ::: "memory");
    __syncthreads();

    int mw = wid & 1, nh = wid >> 1;
    int mi = lane >> 3;
    uint smAhi = smb + G_AHI;
    uint smBh = smb + G_BHI;

    for (int step = 0; step < 3; ++step) {
        float acc[16][4];
        #pragma unroll
        for (int i = 0; i < 16; ++i)
            #pragma unroll
            for (int j = 0; j < 4; ++j) acc[i][j] = 0.0f;

        #pragma unroll
        for (int kt = 0; kt < 4; ++kt) {
            uint a0[4], a1[4];
            {
                int arow = mw * 32 + (lane & 7) + (mi & 1) * 8;
                int ac = 2 * kt + (mi >> 1);
                uint aoff = (uint)(arow * 128 + ((ac ^ (arow & 7)) << 4));
                ldsm4(a0, smAhi + aoff);
                ldsm4(a1, smAhi + aoff + 16 * 128);
            }
            #pragma unroll
            for (int g2 = 0; g2 < 4; ++g2) {
                uint bh[4];
                int nrow = nh * 64 + g2 * 16 + (mi >> 1) * 8 + (lane & 7);
                int bc = 2 * kt + (mi & 1);
                uint boff = (uint)(nrow * 128 + ((bc ^ (nrow & 7)) << 4));
                ldsm4(bh, smBh + boff);
                mma16816(acc[0 * 8 + g2 * 2],     a0, bh);
                mma16816(acc[0 * 8 + g2 * 2 + 1], a0, bh + 2);
                mma16816(acc[1 * 8 + g2 * 2],     a1, bh);
                mma16816(acc[1 * 8 + g2 * 2 + 1], a1, bh + 2);
            }
        }
        __syncthreads();   // A reads complete before gates overwrite A/hS

        // gates -> h' (writes hS fp32 AND A fp16 in place)
        {
            int qj = lane & 3;
            int rb = lane >> 2;
            #pragma unroll
            for (int mt = 0; mt < 2; ++mt) {
                #pragma unroll
                for (int tp = 0; tp < 4; ++tp) {
                    float* aRZ = acc[mt * 8 + tp];
                    float* aNH = acc[mt * 8 + tp + 4];
                    int cb = nh * 64 + tp * 8 + 2 * qj;
                    float br = biasS[cb],      bz = biasS[cb + 1];
                    float bi = biasS[cb + 32], bn = biasS[cb + 33];
                    int j = nh * 16 + tp * 4 + qj;
                    int ra = mw * 32 + mt * 16 + rb;
                    {
                        float r = fast_sigm(aRZ[0] + br), z = fast_sigm(aRZ[1] + bz);
                        float nv = fast_tanh((aNH[0] + bi) + r * (aNH[1] + bn));
                        float hnew = (1.0f - z) * nv + z * hS[ra * 65 + j];
                        hS[ra * 65 + j] = hnew;
                        sts16(smb + G_AHI + a16_off(ra, j), __float2half_rn(hnew));
                    }
                    {
                        float r = fast_sigm(aRZ[2] + br), z = fast_sigm(aRZ[3] + bz);
                        float nv = fast_tanh((aNH[2] + bi) + r * (aNH[3] + bn));
                        float hnew = (1.0f - z) * nv + z * hS[(ra + 8) * 65 + j];
                        hS[(ra + 8) * 65 + j] = hnew;
                        sts16(smb + G_AHI + a16_off(ra + 8, j), __float2half_rn(hnew));
                    }
                }
            }
        }
        __syncthreads();   // A writes visible before next GEMM
    }

    // coalesced writeback
    #pragma unroll
    for (int j = 0; j < 16; ++j) {
        int idx = j * 256 + t;
        int r = idx >> 6, c = idx & 63;
        int n = n0 + r;
        if (n < N) g_out[(size_t)n * 64 + c] = hS[r * 65 + c];
    }
}

// ---------------- Set2Set LSTM step: 32 graphs/block, weights staged once (cp.async) ----------------
#define L_WST 0          // 256 rows x 33 float4 = 135168 B
#define L_IN  135168     // 32 x 32 float4 = 16384 B
#define L_GS  151552     // 32 x 256 f32 = 32768 B
#define LSTM_SMEM 184320

__global__ void __launch_bounds__(256, 1) lstm_kernel(
    const float* __restrict__ bih, const float* __restrict__ bhh, int B)
{
    extern __shared__ char lsm[];
    uint smb = smem_u32(lsm);
    float4* wst4 = (float4*)(lsm + L_WST);
    float4* in4  = (float4*)(lsm + L_IN);
    float*  gsm  = (float*)(lsm + L_GS);
    int t = threadIdx.x;
    int b0 = blockIdx.x * 32;

    // stage weights once via cp.async: 8192 float4
    for (int i = t; i < 8192; i += 256) {
        uint dst = smb + L_WST + (uint)(((i >> 5) * 33 + (i & 31)) * 16);
        cp16(dst, (const char*)g_LW + (size_t)i * 16);
    }
    asm volatile("cp.async.commit_group;");

    // stage inputs: [32 graphs][128] = [hl(64) | rg(64)]
    for (int i = t; i < 1024; i += 256) {
        int g = i >> 5, q = i & 31;
        int b = b0 + g;
        float4 v = make_float4(0.f, 0.f, 0.f, 0.f);
        if (b < B) {
            if (q < 16) v = *(const float4*)(g_S + b * 192 + 128 + q * 4);
            else        v = *(const float4*)(g_S + b * 192 + 64 + (q - 16) * 4);
        }
        in4[g * 32 + q] = v;
    }
    float bsum = bih[t] + bhh[t];
    asm volatile("cp.async.wait_group 0;" ::: "memory");
    __syncthreads();

    float acc[32];
    #pragma unroll
    for (int g = 0; g < 32; ++g) acc[g] = bsum;

    for (int q = 0; q < 32; ++q) {
        float4 w = wst4[t * 33 + q];
        #pragma unroll
        for (int g = 0; g < 32; ++g) {
            float4 v = in4[g * 32 + q];
            acc[g] = fmaf(w.x, v.x, fmaf(w.y, v.y, fmaf(w.z, v.z, fmaf(w.w, v.w, acc[g]))));
        }
    }

    #pragma unroll
    for (int g = 0; g < 32; ++g) gsm[g * 256 + t] = acc[g];
    __syncthreads();

    for (int i = t; i < 32 * 64; i += 256) {
        int g = i >> 6, hh = i & 63;
        int b = b0 + g;
        if (b >= B) continue;
        float ig = fast_sigm(gsm[g * 256 + hh]);
        float fg = fast_sigm(gsm[g * 256 + 64 + hh]);
        float gg = fast_tanh(gsm[g * 256 + 128 + hh]);
        float og = fast_sigm(gsm[g * 256 + 192 + hh]);
        float cnew = fg * g_cl[b * 64 + hh] + ig * gg;
        g_cl[b * 64 + hh] = cnew;
        g_S[b * 192 + 128 + hh] = og * fast_tanh(cnew);
    }
}

// ---------------- Set2Set attention step (128 threads / graph) ----------------
__global__ void __launch_bounds__(128) attn_kernel(int B, int write_q)
{
    __shared__ float qs[64];
    __shared__ float wm[4], ws[4];
    __shared__ float rgS[64];
    int t = threadIdx.x, b = blockIdx.x;
    if (t < 64) qs[t] = g_S[b * 192 + 128 + t];
    __syncthreads();
    int n0 = g_seg[b], n1 = g_seg[b + 1];
    int w = t >> 5, lid = t & 31;

    float mr = -1e30f, sr = 0.0f;
    for (int n = n0 + w; n < n1; n += 4) {
        const float* orow = g_out + (size_t)n * 64;
        float p = orow[lid] * qs[lid] + orow[32 + lid] * qs[32 + lid];
        #pragma unroll
        for (int off = 16; off; off >>= 1) p += __shfl_xor_sync(0xffffffffu, p, off);
        if (lid == 0) g_cnt[n] = p;
        if (p > mr) { sr *= __expf(mr - p); mr = p; }
        sr += __expf(p - mr);
    }
    if (lid == 0) { wm[w] = mr; ws[w] = sr; }
    __syncthreads();
    float m = fmaxf(fmaxf(wm[0], wm[1]), fmaxf(wm[2], wm[3]));
    float denom = ws[0] * __expf(wm[0] - m) + ws[1] * __expf(wm[1] - m)
                + ws[2] * __expf(wm[2] - m) + ws[3] * __expf(wm[3] - m);

    int col = t & 63, half = t >> 6;
    float rg = 0.0f;
    for (int n = n0 + half; n < n1; n += 2)
        rg = fmaf(__expf(g_cnt[n] - m), g_out[(size_t)n * 64 + col], rg);
    if (half) rgS[col] = rg;
    __syncthreads();
    if (!half) {
        rg += rgS[col];
        if (n1 > n0) rg /= denom;
        if (write_q) g_S[b * 192 + col] = qs[col];
        g_S[b * 192 + 64 + col] = rg;
    }
}

// ---------------- readout: 32 graphs/block, fc1 staged in smem ----------------
#define R_W1  0          // 128 x 65 f32 = 33280
#define R_QS  33280      // 32 x 128 f32 = 16384
#define R_RED 49664      // 8 warps x 8 g = 256
#define RD_SMEM 49920

__global__ void __launch_bounds__(256, 1) readout_kernel(
    const float* __restrict__ fc1_w, const float* __restrict__ fc1_b,
    const float* __restrict__ fc2_w, const float* __restrict__ fc2_b,
    float* __restrict__ y, int B)
{
    extern __shared__ char rsm[];
    float* w1S = (float*)(rsm + R_W1);
    float* qsm = (float*)(rsm + R_QS);
    float* red = (float*)(rsm + R_RED);
    int t = threadIdx.x;
    int sub = t >> 6, col = t & 63;
    int b0 = blockIdx.x * 32;

    for (int i = t; i < 8192; i += 256) {
        int k = i >> 6, c = i & 63;
        w1S[k * 65 + c] = fc1_w[i];
    }
    for (int i = t; i < 4096; i += 256) {
        int g = i >> 7, k = i & 127;
        int b = b0 + g;
        qsm[i] = (b < B) ? g_S[b * 192 + k] : 0.0f;
    }
    __syncthreads();

    float acc[8];
    float b1v = fc1_b[col];
    #pragma unroll
    for (int g = 0; g < 8; ++g) acc[g] = b1v;
    for (int k = 0; k < 128; ++k) {
        float w = w1S[k * 65 + col];
        #pragma unroll
        for (int g = 0; g < 8; ++g)
            acc[g] = fmaf(w, qsm[(sub * 8 + g) * 128 + k], acc[g]);
    }

    float w2 = fc2_w[col];
    int wi = t >> 5;
    #pragma unroll
    for (int g = 0; g < 8; ++g) {
        float p = fmaxf(acc[g], 0.0f) * w2;
        #pragma unroll
        for (int off = 16; off; off >>= 1) p += __shfl_xor_sync(0xffffffffu, p, off);
        if ((t & 31) == 0) red[wi * 8 + g] = p;
    }
    __syncthreads();
    if (t < 32) {
        int s = t >> 3, g = t & 7;
        int b = b0 + s * 8 + g;
        if (b < B) y[b] = red[(2 * s) * 8 + g] + red[(2 * s + 1) * 8 + g] + fc2_b[0];
    }
}

// ---------------- launch ----------------
extern "C" void kernel_launch(void* const* d_in, const int* in_sizes, int n_in,
                              void* d_out, int out_size)
{
    const float* x         = (const float*)d_in[0];
    const float* edge_attr = (const float*)d_in[1];
    const int*   edge_index= (const int*)  d_in[2];
    const int*   batch     = (const int*)  d_in[3];
    const float* w_e1      = (const float*)d_in[4];
    const float* b_e1      = (const float*)d_in[5];
    const float* w_e2      = (const float*)d_in[6];
    const float* b_e2      = (const float*)d_in[7];
    const float* root      = (const float*)d_in[8];
    const float* conv_bias = (const float*)d_in[9];
    const float* gru_wih   = (const float*)d_in[10];
    const float* gru_whh   = (const float*)d_in[11];
    const float* gru_bih   = (const float*)d_in[12];
    const float* gru_bhh   = (const float*)d_in[13];
    const float* lstm_wih  = (const float*)d_in[14];
    const float* lstm_whh  = (const float*)d_in[15];
    const float* lstm_bih  = (const float*)d_in[16];
    const float* lstm_bhh  = (const float*)d_in[17];
    const float* fc1_w     = (const float*)d_in[18];
    const float* fc1_b     = (const float*)d_in[19];
    const float* fc2_w     = (const float*)d_in[20];
    const float* fc2_b     = (const float*)d_in[21];
    float* y = (float*)d_out;

    int N = in_sizes[0] / 16;
    int E = in_sizes[1] / 4;
    int B = out_size;

    static int smem_set = 0;
    if (!smem_set) {
        cudaFuncSetAttribute(edge_kernel3, cudaFuncAttributeMaxDynamicSharedMemorySize, EK3_SMEM);
        cudaFuncSetAttribute(gru_node_kernel, cudaFuncAttributeMaxDynamicSharedMemorySize, GRU_SMEM);
        cudaFuncSetAttribute(lstm_kernel, cudaFuncAttributeMaxDynamicSharedMemorySize, LSTM_SMEM);
        cudaFuncSetAttribute(readout_kernel, cudaFuncAttributeMaxDynamicSharedMemorySize, RD_SMEM);
        smem_set = 1;
    }

    // lstm#1 hoisted before gru (depends only on setup zeros) -> gru_node is launch #4 (ncu window)
    setup_kernel<<<SETUP_BLOCKS, 256>>>(w_e2, gru_wih, gru_whh, gru_bih, gru_bhh,
                                        lstm_wih, lstm_whh, batch, N, B);
    edge_kernel3<<<(E + 127) / 128, 256, EK3_SMEM>>>(x, edge_attr, edge_index, w_e1, b_e1, b_e2, E);
    lstm_kernel<<<(B + 31) / 32, 256, LSTM_SMEM>>>(lstm_bih, lstm_bhh, B);
    gru_node_kernel<<<(N + 63) / 64, 256, GRU_SMEM>>>(x, root, conv_bias, N);
    attn_kernel<<<B, 128>>>(B, 0);
    for (int i = 1; i < 3; ++i) {
        lstm_kernel<<<(B + 31) / 32, 256, LSTM_SMEM>>>(lstm_bih, lstm_bhh, B);
        attn_kernel<<<B, 128>>>(B, i == 2);
    }
    readout_kernel<<<(B + 7 * 4 + 31) / 32, 256, RD_SMEM>>>(fc1_w, fc1_b, fc2_w, fc2_b, y, B);
}